// round 12
// baseline (speedup 1.0000x reference)
#include <cuda_runtime.h>
#include <math.h>

#define NTOK 80000
#define KK   4
#define ROWS 32
#define NTHR 512

typedef unsigned long long ull;

// ---------------- f32x2 packed helpers ----------------
__device__ __forceinline__ ull pk2(float lo, float hi) {
    ull r;
    asm("mov.b64 %0, {%1, %2};" : "=l"(r) : "r"(__float_as_uint(lo)), "r"(__float_as_uint(hi)));
    return r;
}
__device__ __forceinline__ void upk2(float& lo, float& hi, ull v) {
    unsigned int a, b;
    asm("mov.b64 {%0, %1}, %2;" : "=r"(a), "=r"(b) : "l"(v));
    lo = __uint_as_float(a); hi = __uint_as_float(b);
}
__device__ __forceinline__ ull ffma2(ull a, ull b, ull c) {
    ull d;
    asm("fma.rn.f32x2 %0, %1, %2, %3;" : "=l"(d) : "l"(a), "l"(b), "l"(c));
    return d;
}
__device__ __forceinline__ ull fmul2(ull a, ull b) {
    ull d;
    asm("mul.rn.f32x2 %0, %1, %2;" : "=l"(d) : "l"(a), "l"(b));
    return d;
}

// ---------------- smem layout (float offsets), ~209 KB -> 1 CTA/SM, 32 rows ----------------
constexpr int OFF_SCUR = 0;                   // 32*256 = 8192   (U1_T scratch during op4, stride 36)
constexpr int OFF_VCUR = OFF_SCUR + 8192;     // 32*384 = 12288  (U0_T scratch during op4, stride 36)
constexpr int OFF_XS   = OFF_VCUR + 12288;    // transposed x, stride 36: 192*36 = 6912
constexpr int OFF_TMP  = OFF_XS   + 6912;     // transposed [s_k|n_k|p0], stride 36: 161*36 = 5796 (+pad)
constexpr int OFF_VKA  = OFF_TMP  + 5832;     // transposed v_k, stride 36: 192*36 = 6912
constexpr int OFF_VKB  = OFF_VKA  + 6912;     // 6912
constexpr int OFF_MBUF = OFF_VKB  + 6912;     // 32*128 = 4096 (m-norms; MLP partial buf)
constexpr int OFF_GB   = OFF_MBUF + 4096;     // gamma 384 + beta 384
constexpr int OFF_BM1  = OFF_GB   + 768;      // 64
constexpr int OFF_WM2  = OFF_BM1  + 64;       // 64
constexpr int OFF_SP1  = OFF_WM2  + 64;       // 32*4
constexpr int OFF_EV   = OFF_SP1  + 128;      // 32*4
constexpr int SMEM_FLOATS = OFF_EV + 128;     // 52260 floats
constexpr int SMEM_BYTES  = SMEM_FLOATS * 4;  // 209040 B -> 1 block/SM
// hbuf (row-major LN output, 32*384=12288) overlays freed XS+TMP (6912+5832=12744)
constexpr int OFF_HBUF = OFF_XS;

// ---------------- global scratch (no allocs allowed) ----------------
__device__ __align__(16) float g_SV[(size_t)NTOK * 2560];  // [row][k][640] : S(256) then V(384)

__global__ void __launch_bounds__(NTHR, 1)
fuse_k1(const float* __restrict__ x0, const float* __restrict__ x1,
        const float* __restrict__ x2, const float* __restrict__ x3,
        const float* __restrict__ W_l0, const float* __restrict__ W_l1,
        const float* __restrict__ W_l2, const float* __restrict__ W_tp0,
        const float* __restrict__ W_tp1, const float* __restrict__ Ws,
        const float* __restrict__ bs, const float* __restrict__ Wv1o,
        const float* __restrict__ Wv1e, const float* __restrict__ gamma,
        const float* __restrict__ beta, const float* __restrict__ Wm1,
        const float* __restrict__ bm1, const float* __restrict__ Wm2,
        const float* __restrict__ bm2, float* __restrict__ out)
{
    extern __shared__ float sm[];
    const int t  = threadIdx.x;
    const int r0 = blockIdx.x * ROWS;

    for (int i = t; i < 384; i += NTHR) { sm[OFF_GB + i] = gamma[i]; sm[OFF_GB + 384 + i] = beta[i]; }
    if (t < 64) { sm[OFF_BM1 + t] = bm1[t]; sm[OFF_WM2 + t] = Wm2[t]; }
    __syncthreads();

    const float* xs_ptr[KK] = {x0, x1, x2, x3};
    float* vkbuf = sm + OFF_VKA;   // transposed [(j*3+m)*36 + r]
    float* vpbuf = sm + OFF_VKB;

    for (int k = 0; k < KK; ++k) {
        const float* xg = xs_ptr[k];

        // ---- stage x_s (transposed, stride 36) ----
        for (int idx = t; idx < ROWS*128; idx += NTHR) {
            int r = idx >> 7, c = idx & 127;
            sm[OFF_XS + c*36 + r] = xg[(size_t)(r0 + r)*480 + c];
        }
        __syncthreads();

        // ---- op1: s_k = x_s @ W_l0 * inv0  (4 col-groups x 8 rows, packed) ----
        {
            int j = t & 127, rq = t >> 7;            // 4 groups of 8 rows
            ull a01 = 0, a23 = 0, a45 = 0, a67 = 0;
            const float* W = W_l0 + k*128*128;
            #pragma unroll 8
            for (int i = 0; i < 128; ++i) {
                float w = __ldg(&W[i*128 + j]);
                ull ww = pk2(w, w);
                const ulonglong2 xa = *reinterpret_cast<const ulonglong2*>(&sm[OFF_XS + i*36 + rq*8]);
                const ulonglong2 xb = *reinterpret_cast<const ulonglong2*>(&sm[OFF_XS + i*36 + rq*8 + 4]);
                a01 = ffma2(xa.x, ww, a01);
                a23 = ffma2(xa.y, ww, a23);
                a45 = ffma2(xb.x, ww, a45);
                a67 = ffma2(xb.y, ww, a67);
            }
            const ull ss = pk2(0.08838834764831845f, 0.08838834764831845f);  // 1/sqrt(128)
            *reinterpret_cast<ull*>(&sm[OFF_TMP + j*36 + rq*8    ]) = fmul2(a01, ss);
            *reinterpret_cast<ull*>(&sm[OFF_TMP + j*36 + rq*8 + 2]) = fmul2(a23, ss);
            *reinterpret_cast<ull*>(&sm[OFF_TMP + j*36 + rq*8 + 4]) = fmul2(a45, ss);
            *reinterpret_cast<ull*>(&sm[OFF_TMP + j*36 + rq*8 + 6]) = fmul2(a67, ss);
        }
        __syncthreads();

        // ---- stage x_v (192 cols) ----
        for (int idx = t; idx < ROWS*192; idx += NTHR) {
            int r = idx / 192, c = idx - r*192;
            sm[OFF_XS + c*36 + r] = xg[(size_t)(r0 + r)*480 + 128 + c];
        }
        __syncthreads();

        // ---- op2: v_k -> vk_T stride 36 (8 col-groups x 4 rows) ----
        {
            int j = t & 63, rg = t >> 6;             // 8 groups of 4 rows
            ull a0l=0,a0h=0, a1l=0,a1h=0, a2l=0,a2h=0;
            const float* W = W_l1 + k*64*64;
            #pragma unroll 8
            for (int i = 0; i < 64; ++i) {
                float w = __ldg(&W[i*64 + j]);
                ull ww = pk2(w, w);
                const ulonglong2 x0v = *reinterpret_cast<const ulonglong2*>(&sm[OFF_XS + (i*3 + 0)*36 + rg*4]);
                const ulonglong2 x1v = *reinterpret_cast<const ulonglong2*>(&sm[OFF_XS + (i*3 + 1)*36 + rg*4]);
                const ulonglong2 x2v = *reinterpret_cast<const ulonglong2*>(&sm[OFF_XS + (i*3 + 2)*36 + rg*4]);
                a0l = ffma2(x0v.x, ww, a0l); a0h = ffma2(x0v.y, ww, a0h);
                a1l = ffma2(x1v.x, ww, a1l); a1h = ffma2(x1v.y, ww, a1h);
                a2l = ffma2(x2v.x, ww, a2l); a2h = ffma2(x2v.y, ww, a2h);
            }
            const ull ei = pk2(0.125f, 0.125f);
            ulonglong2 s0; s0.x = fmul2(a0l, ei); s0.y = fmul2(a0h, ei);
            ulonglong2 s1; s1.x = fmul2(a1l, ei); s1.y = fmul2(a1h, ei);
            ulonglong2 s2; s2.x = fmul2(a2l, ei); s2.y = fmul2(a2h, ei);
            *reinterpret_cast<ulonglong2*>(&vkbuf[(j*3 + 0)*36 + rg*4]) = s0;
            *reinterpret_cast<ulonglong2*>(&vkbuf[(j*3 + 1)*36 + rg*4]) = s1;
            *reinterpret_cast<ulonglong2*>(&vkbuf[(j*3 + 2)*36 + rg*4]) = s2;
        }
        __syncthreads();

        // ---- stage x_T (160 cols) ----
        for (int idx = t; idx < ROWS*160; idx += NTHR) {
            int r = idx / 160, c = idx - r*160;
            sm[OFF_XS + c*36 + r] = xg[(size_t)(r0 + r)*480 + 320 + c];
        }
        __syncthreads();

        // ---- op3 (all threads): n_k into TMP, 2 rows/thread packed ----
        {
            int j = t & 31, rp = (t >> 5)*2;         // 16 groups of 2 rows
            ull a[5] = {};
            const float* W = W_l2 + k*32*32;
            #pragma unroll 8
            for (int i = 0; i < 32; ++i) {
                float w = __ldg(&W[i*32 + j]);
                ull ww = pk2(w, w);
                #pragma unroll
                for (int m = 0; m < 5; ++m)
                    a[m] = ffma2(*reinterpret_cast<const ull*>(&sm[OFF_XS + (i*5 + m)*36 + rp]), ww, a[m]);
            }
            float sa = 0.f, sb = 0.f;
            #pragma unroll
            for (int m = 0; m < 5; ++m) {
                float lo, hi; upk2(lo, hi, a[m]);
                sa += lo*lo; sb += hi*hi;
            }
            sm[OFF_TMP + (128 + j)*36 + rp    ] = sqrtf(sa)*0.17677669529663687f;  // 1/sqrt(32)
            sm[OFF_TMP + (128 + j)*36 + rp + 1] = sqrtf(sb)*0.17677669529663687f;
        }

        // ---- op4-GEMM (all threads): U0_T -> VCUR, U1_T -> SCUR (stride 36) ----
        if (k > 0) {
            int j = t & 63, rg = t >> 6;             // 8 groups of 4 rows
            ull u0[3][2] = {}, u1[3][2] = {};
            #pragma unroll 4
            for (int i = 0; i < 64; ++i) {
                float w0 = __ldg(&W_tp0[i*64 + j]);
                float w1 = __ldg(&W_tp1[i*64 + j]);
                ull ww0 = pk2(w0, w0), ww1 = pk2(w1, w1);
                #pragma unroll
                for (int m = 0; m < 3; ++m) {
                    const ulonglong2 vp = *reinterpret_cast<const ulonglong2*>(&vkbuf[(i*3 + m)*36 + rg*4]);
                    u0[m][0] = ffma2(vp.x, ww0, u0[m][0]);
                    u0[m][1] = ffma2(vp.y, ww0, u0[m][1]);
                    u1[m][0] = ffma2(vp.x, ww1, u1[m][0]);
                    u1[m][1] = ffma2(vp.y, ww1, u1[m][1]);
                }
            }
            #pragma unroll
            for (int m = 0; m < 3; ++m) {
                ulonglong2 s0; s0.x = u0[m][0]; s0.y = u0[m][1];
                ulonglong2 s1; s1.x = u1[m][0]; s1.y = u1[m][1];
                *reinterpret_cast<ulonglong2*>(&sm[OFF_VCUR + (j*3 + m)*36 + rg*4]) = s0;
                *reinterpret_cast<ulonglong2*>(&sm[OFF_SCUR + (j*3 + m)*36 + rg*4]) = s1;
            }
        }
        __syncthreads();

        // ---- op4-reduce: p0/p1 (16 warps, 2 rows/warp) ----
        if (k > 0) {
            int w = t >> 5, lane = t & 31;
            int ra = 2*w, rb = 2*w + 1;
            float p0a=0,pxa=0,pya=0,pza=0, p0b=0,pxb=0,pyb=0,pzb=0;
            #pragma unroll
            for (int jj = 0; jj < 2; ++jj) {
                int j = jj*32 + lane;
                float u00 = sm[OFF_VCUR + (j*3+0)*36 + ra];
                float u01 = sm[OFF_VCUR + (j*3+1)*36 + ra];
                float u02 = sm[OFF_VCUR + (j*3+2)*36 + ra];
                float u10 = sm[OFF_SCUR + (j*3+0)*36 + ra];
                float u11 = sm[OFF_SCUR + (j*3+1)*36 + ra];
                float u12 = sm[OFF_SCUR + (j*3+2)*36 + ra];
                float vx = vpbuf[(j*3+0)*36 + ra];
                float vy = vpbuf[(j*3+1)*36 + ra];
                float vz = vpbuf[(j*3+2)*36 + ra];
                p0a += u00*vx + u01*vy + u02*vz;
                pxa += u11*vz - u12*vy;
                pya += u12*vx - u10*vz;
                pza += u10*vy - u11*vx;
                u00 = sm[OFF_VCUR + (j*3+0)*36 + rb];
                u01 = sm[OFF_VCUR + (j*3+1)*36 + rb];
                u02 = sm[OFF_VCUR + (j*3+2)*36 + rb];
                u10 = sm[OFF_SCUR + (j*3+0)*36 + rb];
                u11 = sm[OFF_SCUR + (j*3+1)*36 + rb];
                u12 = sm[OFF_SCUR + (j*3+2)*36 + rb];
                vx = vpbuf[(j*3+0)*36 + rb];
                vy = vpbuf[(j*3+1)*36 + rb];
                vz = vpbuf[(j*3+2)*36 + rb];
                p0b += u00*vx + u01*vy + u02*vz;
                pxb += u11*vz - u12*vy;
                pyb += u12*vx - u10*vz;
                pzb += u10*vy - u11*vx;
            }
            #pragma unroll
            for (int off = 16; off > 0; off >>= 1) {
                p0a += __shfl_down_sync(0xffffffffu, p0a, off);
                pxa += __shfl_down_sync(0xffffffffu, pxa, off);
                pya += __shfl_down_sync(0xffffffffu, pya, off);
                pza += __shfl_down_sync(0xffffffffu, pza, off);
                p0b += __shfl_down_sync(0xffffffffu, p0b, off);
                pxb += __shfl_down_sync(0xffffffffu, pxb, off);
                pyb += __shfl_down_sync(0xffffffffu, pyb, off);
                pzb += __shfl_down_sync(0xffffffffu, pzb, off);
            }
            if (lane == 0) {
                const float c0 = 0.009021097956087905f;   // 1/(sqrt(3)*64)
                const float c1 = 0.011048543456039806f;   // 1/(sqrt(2)*64)
                sm[OFF_TMP + 160*36 + ra] = p0a*c0;
                sm[OFF_SP1 + ra*4 + 0] = pxa*c1;
                sm[OFF_SP1 + ra*4 + 1] = pya*c1;
                sm[OFF_SP1 + ra*4 + 2] = pza*c1;
                sm[OFF_TMP + 160*36 + rb] = p0b*c0;
                sm[OFF_SP1 + rb*4 + 0] = pxb*c1;
                sm[OFF_SP1 + rb*4 + 1] = pyb*c1;
                sm[OFF_SP1 + rb*4 + 2] = pzb*c1;
            }
        } else {
            if (t < ROWS) {
                sm[OFF_TMP + 160*36 + t] = 0.f;
                sm[OFF_SP1 + t*4 + 0] = 0.f;
                sm[OFF_SP1 + t*4 + 1] = 0.f;
                sm[OFF_SP1 + t*4 + 2] = 0.f;
            }
        }
        __syncthreads();

        // ---- op5: s_tilde (2 cols x 8 rows per thread, packed) ----
        {
            int c2 = (t & 127) * 2, h4 = t >> 7;     // 4 groups of 8 rows
            ull aA[4] = {}, aB[4] = {};
            const float* W = Ws + k*161*256;
            #pragma unroll 8
            for (int i = 0; i < 161; ++i) {
                const float2 w = *reinterpret_cast<const float2*>(&W[i*256 + c2]);
                ull wx = pk2(w.x, w.x), wy = pk2(w.y, w.y);
                const ulonglong2 xa = *reinterpret_cast<const ulonglong2*>(&sm[OFF_TMP + i*36 + h4*8]);
                const ulonglong2 xb = *reinterpret_cast<const ulonglong2*>(&sm[OFF_TMP + i*36 + h4*8 + 4]);
                aA[0] = ffma2(xa.x, wx, aA[0]);
                aA[1] = ffma2(xa.y, wx, aA[1]);
                aA[2] = ffma2(xb.x, wx, aA[2]);
                aA[3] = ffma2(xb.y, wx, aA[3]);
                aB[0] = ffma2(xa.x, wy, aB[0]);
                aB[1] = ffma2(xa.y, wy, aB[1]);
                aB[2] = ffma2(xb.x, wy, aB[2]);
                aB[3] = ffma2(xb.y, wy, aB[3]);
            }
            const float2 bb = *reinterpret_cast<const float2*>(&bs[k*256 + c2]);
            #pragma unroll
            for (int q = 0; q < 4; ++q) {
                float alo, ahi, blo, bhi;
                upk2(alo, ahi, aA[q]); upk2(blo, bhi, aB[q]);
                float2 o;
                o.x = alo + bb.x; o.y = blo + bb.y;
                *reinterpret_cast<float2*>(&sm[OFF_SCUR + (h4*8 + q*2    )*256 + c2]) = o;
                o.x = ahi + bb.x; o.y = bhi + bb.y;
                *reinterpret_cast<float2*>(&sm[OFF_SCUR + (h4*8 + q*2 + 1)*256 + c2]) = o;
            }
        }

        // ---- op6: v1o, v1e -> Vcur (row-major), 8 col-groups x 4 rows ----
        {
            int j = t & 63, rg = t >> 6;
            ull a0l=0,a0h=0, a1l=0,a1h=0, a2l=0,a2h=0;
            const float* W = Wv1o + k*64*64;
            #pragma unroll 8
            for (int i = 0; i < 64; ++i) {
                float w = __ldg(&W[i*64 + j]);
                ull ww = pk2(w, w);
                const ulonglong2 v0v = *reinterpret_cast<const ulonglong2*>(&vkbuf[(i*3 + 0)*36 + rg*4]);
                const ulonglong2 v1v = *reinterpret_cast<const ulonglong2*>(&vkbuf[(i*3 + 1)*36 + rg*4]);
                const ulonglong2 v2v = *reinterpret_cast<const ulonglong2*>(&vkbuf[(i*3 + 2)*36 + rg*4]);
                a0l = ffma2(v0v.x, ww, a0l); a0h = ffma2(v0v.y, ww, a0h);
                a1l = ffma2(v1v.x, ww, a1l); a1h = ffma2(v1v.y, ww, a1h);
                a2l = ffma2(v2v.x, ww, a2l); a2h = ffma2(v2v.y, ww, a2h);
            }
            float we = __ldg(&Wv1e[k*64 + j]);
            float f[3][4];
            upk2(f[0][0], f[0][1], a0l); upk2(f[0][2], f[0][3], a0h);
            upk2(f[1][0], f[1][1], a1l); upk2(f[1][2], f[1][3], a1h);
            upk2(f[2][0], f[2][1], a2l); upk2(f[2][2], f[2][3], a2h);
            #pragma unroll
            for (int rr = 0; rr < 4; ++rr) {
                int r = rg*4 + rr;
                sm[OFF_VCUR + r*384 + j*3 + 0] = f[0][rr]*0.125f;
                sm[OFF_VCUR + r*384 + j*3 + 1] = f[1][rr]*0.125f;
                sm[OFF_VCUR + r*384 + j*3 + 2] = f[2][rr]*0.125f;
                sm[OFF_VCUR + r*384 + 192 + j*3 + 0] = sm[OFF_SP1 + r*4 + 0]*we;
                sm[OFF_VCUR + r*384 + 192 + j*3 + 1] = sm[OFF_SP1 + r*4 + 1]*we;
                sm[OFF_VCUR + r*384 + 192 + j*3 + 2] = sm[OFF_SP1 + r*4 + 2]*we;
            }
        }
        __syncthreads();

        // ---- layernorm (warp per 2 rows) w/ fused m-norms; writes HBUF ----
        {
            int w = t >> 5, lane = t & 31;
            #pragma unroll
            for (int rr = 0; rr < 2; ++rr) {
                int r = w*2 + rr;
                float s = 0.f, s2 = 0.f;
                #pragma unroll
                for (int c = lane; c < 384; c += 32) {
                    float v;
                    if (c < 256) v = sm[OFF_SCUR + r*256 + c];
                    else {
                        int idx = c - 256;
                        float a = sm[OFF_VCUR + r*384 + idx*3];
                        float b = sm[OFF_VCUR + r*384 + idx*3 + 1];
                        float d = sm[OFF_VCUR + r*384 + idx*3 + 2];
                        v = sqrtf(a*a + b*b + d*d);
                        sm[OFF_MBUF + r*128 + idx] = v;
                    }
                    s += v; s2 += v*v;
                }
                #pragma unroll
                for (int off = 16; off > 0; off >>= 1) {
                    s  += __shfl_xor_sync(0xffffffffu, s,  off);
                    s2 += __shfl_xor_sync(0xffffffffu, s2, off);
                }
                float mu   = s  * (1.f/384.f);
                float var  = s2 * (1.f/384.f) - mu*mu;
                float rstd = rsqrtf(var + 1e-5f);
                #pragma unroll
                for (int c = lane; c < 384; c += 32) {
                    float v = (c < 256) ? sm[OFF_SCUR + r*256 + c] : sm[OFF_MBUF + r*128 + c - 256];
                    sm[OFF_HBUF + r*384 + c] = (v - mu)*rstd*sm[OFF_GB + c] + sm[OFF_GB + 384 + c];
                }
                if (lane == 0) sm[OFF_EV + r*4 + k] = 0.f;
            }
        }
        // spill S,V (float4, all threads)
        for (int idx = t; idx < ROWS*160; idx += NTHR) {
            int r = idx / 160, q = idx - r*160;
            float4 v;
            if (q < 64) v = *reinterpret_cast<const float4*>(&sm[OFF_SCUR + r*256 + q*4]);
            else        v = *reinterpret_cast<const float4*>(&sm[OFF_VCUR + r*384 + (q - 64)*4]);
            *reinterpret_cast<float4*>(&g_SV[(size_t)(r0 + r)*2560 + (size_t)k*640 + q*4]) = v;
        }
        __syncthreads();

        // ---- MLP: 64 cols x 4 row-groups(8 rows) x 2 i-halves ----
        {
            int c = t & 63, g = (t >> 6) & 3, hh = t >> 8;
            ull acc[8] = {};
            const float* Wp = Wm1 + hh*192*64;
            const int ibase = hh*192;
            #pragma unroll 4
            for (int i = 0; i < 192; i += 4) {
                float w0 = __ldg(&Wp[(i+0)*64 + c]);
                float w1 = __ldg(&Wp[(i+1)*64 + c]);
                float w2 = __ldg(&Wp[(i+2)*64 + c]);
                float w3 = __ldg(&Wp[(i+3)*64 + c]);
                ull wp01 = pk2(w0, w1), wp23 = pk2(w2, w3);
                #pragma unroll
                for (int rr = 0; rr < 8; ++rr) {
                    const ulonglong2 hv = *reinterpret_cast<const ulonglong2*>(&sm[OFF_HBUF + (g*8 + rr)*384 + ibase + i]);
                    acc[rr] = ffma2(hv.x, wp01, acc[rr]);
                    acc[rr] = ffma2(hv.y, wp23, acc[rr]);
                }
            }
            float accs[8];
            #pragma unroll
            for (int rr = 0; rr < 8; ++rr) {
                float lo, hi; upk2(lo, hi, acc[rr]);
                accs[rr] = lo + hi;
            }
            if (hh == 1) {
                float4 p0; p0.x = accs[0]; p0.y = accs[1]; p0.z = accs[2]; p0.w = accs[3];
                float4 p1; p1.x = accs[4]; p1.y = accs[5]; p1.z = accs[6]; p1.w = accs[7];
                *reinterpret_cast<float4*>(&sm[OFF_MBUF + (t - 256)*8    ]) = p0;
                *reinterpret_cast<float4*>(&sm[OFF_MBUF + (t - 256)*8 + 4]) = p1;
            }
            __syncthreads();
            if (hh == 0) {
                const float4 p0 = *reinterpret_cast<const float4*>(&sm[OFF_MBUF + t*8    ]);
                const float4 p1 = *reinterpret_cast<const float4*>(&sm[OFF_MBUF + t*8 + 4]);
                accs[0] += p0.x; accs[1] += p0.y; accs[2] += p0.z; accs[3] += p0.w;
                accs[4] += p1.x; accs[5] += p1.y; accs[6] += p1.z; accs[7] += p1.w;
                float wm2c = sm[OFF_WM2 + c];
                float b1c  = sm[OFF_BM1 + c];
                float ep[8];
                #pragma unroll
                for (int rr = 0; rr < 8; ++rr) {
                    float a = accs[rr] + b1c;
                    ep[rr] = a/(1.f + expf(-a)) * wm2c;
                }
                int lane = t & 31;
                #pragma unroll
                for (int off = 16; off > 0; off >>= 1)
                    #pragma unroll
                    for (int rr = 0; rr < 8; ++rr)
                        ep[rr] += __shfl_down_sync(0xffffffffu, ep[rr], off);
                if (lane == 0) {
                    #pragma unroll
                    for (int rr = 0; rr < 8; ++rr)
                        atomicAdd(&sm[OFF_EV + (g*8 + rr)*4 + k], ep[rr]);
                }
            }
        }

        { float* tp = vkbuf; vkbuf = vpbuf; vpbuf = tp; }
        __syncthreads();
    }

    // ---- softmax over K (bm2 cancels); alpha written in place into EV ----
    if (t < ROWS) {
        float e0 = sm[OFF_EV + t*4 + 0], e1 = sm[OFF_EV + t*4 + 1];
        float e2 = sm[OFF_EV + t*4 + 2], e3 = sm[OFF_EV + t*4 + 3];
        float mx = fmaxf(fmaxf(e0, e1), fmaxf(e2, e3));
        float z0 = expf(e0 - mx), z1 = expf(e1 - mx), z2 = expf(e2 - mx), z3 = expf(e3 - mx);
        float inv = 1.f/(z0 + z1 + z2 + z3);
        sm[OFF_EV + t*4 + 0] = z0*inv;
        sm[OFF_EV + t*4 + 1] = z1*inv;
        sm[OFF_EV + t*4 + 2] = z2*inv;
        sm[OFF_EV + t*4 + 3] = z3*inv;
    }
    __syncthreads();

    // ---- fused epilogue: out = sum_k alpha_k * SV_k (L2-hot) ----
    for (int idx = t; idx < ROWS*160; idx += NTHR) {
        int r = idx / 160, q = idx - r*160;
        const float* sv = g_SV + (size_t)(r0 + r)*2560 + q*4;
        const float a0 = sm[OFF_EV + r*4 + 0], a1 = sm[OFF_EV + r*4 + 1];
        const float a2 = sm[OFF_EV + r*4 + 2], a3 = sm[OFF_EV + r*4 + 3];
        const float4 v0 = *reinterpret_cast<const float4*>(sv);
        const float4 v1 = *reinterpret_cast<const float4*>(sv + 640);
        const float4 v2 = *reinterpret_cast<const float4*>(sv + 1280);
        const float4 v3 = *reinterpret_cast<const float4*>(sv + 1920);
        float4 o;
        o.x = a0*v0.x + a1*v1.x + a2*v2.x + a3*v3.x;
        o.y = a0*v0.y + a1*v1.y + a2*v2.y + a3*v3.y;
        o.z = a0*v0.z + a1*v1.z + a2*v2.z + a3*v3.z;
        o.w = a0*v0.w + a1*v1.w + a2*v2.w + a3*v3.w;
        if (q < 64) *reinterpret_cast<float4*>(&out[(size_t)(r0 + r)*256 + q*4]) = o;
        else        *reinterpret_cast<float4*>(&out[(size_t)NTOK*256 + (size_t)(r0 + r)*384 + (q - 64)*4]) = o;
    }
}

extern "C" void kernel_launch(void* const* d_in, const int* in_sizes, int n_in,
                              void* d_out, int out_size)
{
    (void)in_sizes; (void)n_in; (void)out_size;
    cudaFuncSetAttribute(fuse_k1, cudaFuncAttributeMaxDynamicSharedMemorySize, SMEM_BYTES);

    fuse_k1<<<NTOK/ROWS, NTHR, SMEM_BYTES>>>(
        (const float*)d_in[0],  (const float*)d_in[1],  (const float*)d_in[2],
        (const float*)d_in[3],  (const float*)d_in[4],  (const float*)d_in[5],
        (const float*)d_in[6],  (const float*)d_in[7],  (const float*)d_in[8],
        (const float*)d_in[9],  (const float*)d_in[10], (const float*)d_in[11],
        (const float*)d_in[12], (const float*)d_in[13], (const float*)d_in[14],
        (const float*)d_in[15], (const float*)d_in[16], (const float*)d_in[17],
        (const float*)d_in[18], (float*)d_out);
}

// round 13
// speedup vs baseline: 1.3819x; 1.3819x over previous
#include <cuda_runtime.h>
#include <math.h>

#define NTOK 80000
#define KK   4
#define ROWS 16
#define NTHR 512

typedef unsigned long long ull;

// ---------------- f32x2 packed helpers ----------------
__device__ __forceinline__ ull pk2(float lo, float hi) {
    ull r;
    asm("mov.b64 %0, {%1, %2};" : "=l"(r) : "r"(__float_as_uint(lo)), "r"(__float_as_uint(hi)));
    return r;
}
__device__ __forceinline__ void upk2(float& lo, float& hi, ull v) {
    unsigned int a, b;
    asm("mov.b64 {%0, %1}, %2;" : "=r"(a), "=r"(b) : "l"(v));
    lo = __uint_as_float(a); hi = __uint_as_float(b);
}
__device__ __forceinline__ ull ffma2(ull a, ull b, ull c) {
    ull d;
    asm("fma.rn.f32x2 %0, %1, %2, %3;" : "=l"(d) : "l"(a), "l"(b), "l"(c));
    return d;
}
__device__ __forceinline__ ull fmul2(ull a, ull b) {
    ull d;
    asm("mul.rn.f32x2 %0, %1, %2;" : "=l"(d) : "l"(a), "l"(b));
    return d;
}
__device__ __forceinline__ ull fadd2(ull a, ull b) {
    ull d;
    asm("add.rn.f32x2 %0, %1, %2;" : "=l"(d) : "l"(a), "l"(b));
    return d;
}

// ---------------- smem layout (float offsets), ~109 KB -> 2 CTAs/SM ----------------
constexpr int OFF_SCUR = 0;                  // 16*256 = 4096 (op1/MLP partial scratch; U1_T in op4)
constexpr int OFF_VCUR = OFF_SCUR + 4096;    // 16*384 = 6144 (scratch contiguous with SCUR; U0_T in op4)
constexpr int OFF_XS   = OFF_VCUR + 6144;    // transposed x, stride 20: 192*20 = 3840
constexpr int OFF_TMP  = OFF_XS   + 3840;    // transposed [s_k|n_k|p0], stride 20: 161*20 -> 3232
constexpr int OFF_VKA  = OFF_TMP  + 3232;    // transposed v_k, stride 18: 192*18 = 3456
constexpr int OFF_VKB  = OFF_VKA  + 3456;    // 3456
constexpr int OFF_MBUF = OFF_VKB  + 3456;    // 16*128 = 2048 (m-norms)
constexpr int OFF_GB   = OFF_MBUF + 2048;    // gamma 384 + beta 384
constexpr int OFF_BM1  = OFF_GB   + 768;     // 64
constexpr int OFF_WM2  = OFF_BM1  + 64;      // 64
constexpr int OFF_SP1  = OFF_WM2  + 64;      // 16*4
constexpr int OFF_EV   = OFF_SP1  + 64;      // 16*4 (e scores, then alpha)
constexpr int SMEM_FLOATS = OFF_EV + 64;     // 27296 floats
constexpr int SMEM_BYTES  = SMEM_FLOATS * 4; // 109184 B -> 2 blocks/SM
// h_T (transposed LN output, stride 18: 384*18 = 6912) overlays freed XS+TMP (7072)
constexpr int OFF_HBUF = OFF_XS;

// ---------------- global scratch (no allocs allowed) ----------------
__device__ __align__(16) float g_SV[(size_t)NTOK * 2560];  // [row][k][640] : S(256) then V(384)

__global__ void __launch_bounds__(NTHR, 2)
fuse_k1(const float* __restrict__ x0, const float* __restrict__ x1,
        const float* __restrict__ x2, const float* __restrict__ x3,
        const float* __restrict__ W_l0, const float* __restrict__ W_l1,
        const float* __restrict__ W_l2, const float* __restrict__ W_tp0,
        const float* __restrict__ W_tp1, const float* __restrict__ Ws,
        const float* __restrict__ bs, const float* __restrict__ Wv1o,
        const float* __restrict__ Wv1e, const float* __restrict__ gamma,
        const float* __restrict__ beta, const float* __restrict__ Wm1,
        const float* __restrict__ bm1, const float* __restrict__ Wm2,
        const float* __restrict__ bm2, float* __restrict__ out)
{
    extern __shared__ float sm[];
    const int t  = threadIdx.x;
    const int r0 = blockIdx.x * ROWS;

    for (int i = t; i < 384; i += NTHR) { sm[OFF_GB + i] = gamma[i]; sm[OFF_GB + 384 + i] = beta[i]; }
    if (t < 64) { sm[OFF_BM1 + t] = bm1[t]; sm[OFF_WM2 + t] = Wm2[t]; }
    __syncthreads();

    const float* xs_ptr[KK] = {x0, x1, x2, x3};
    float* vkbuf = sm + OFF_VKA;   // transposed [(j*3+m)*18 + r]
    float* vpbuf = sm + OFF_VKB;

    for (int k = 0; k < KK; ++k) {
        const float* xg = xs_ptr[k];

        // ---- stage x_s (transposed, stride 20) ----
        for (int idx = t; idx < ROWS*128; idx += NTHR) {
            int r = idx >> 7, c = idx & 127;
            sm[OFF_XS + c*20 + r] = xg[(size_t)(r0 + r)*480 + c];
        }
        __syncthreads();

        // ---- op1: s_k = x_s @ W_l0 * inv0 ; 4 cols x 4 rows per thread, i-split x4 ----
        {
            const int tl = t & 127;
            const int c4 = (tl & 31) * 4;        // 32 colgroups x 4 cols
            const int rq = tl >> 5;              // 4 rowgroups x 4 rows
            const int g  = t >> 7;               // 4 i-chunks of 32
            ull a[4][2] = {};
            const float* W = W_l0 + k*128*128 + g*32*128;
            #pragma unroll 8
            for (int i = 0; i < 32; ++i) {
                const float4 w4 = *reinterpret_cast<const float4*>(&W[i*128 + c4]);
                const ulonglong2 xv = *reinterpret_cast<const ulonglong2*>(&sm[OFF_XS + (g*32 + i)*20 + rq*4]);
                ull ww;
                ww = pk2(w4.x, w4.x); a[0][0]=ffma2(xv.x,ww,a[0][0]); a[0][1]=ffma2(xv.y,ww,a[0][1]);
                ww = pk2(w4.y, w4.y); a[1][0]=ffma2(xv.x,ww,a[1][0]); a[1][1]=ffma2(xv.y,ww,a[1][1]);
                ww = pk2(w4.z, w4.z); a[2][0]=ffma2(xv.x,ww,a[2][0]); a[2][1]=ffma2(xv.y,ww,a[2][1]);
                ww = pk2(w4.w, w4.w); a[3][0]=ffma2(xv.x,ww,a[3][0]); a[3][1]=ffma2(xv.y,ww,a[3][1]);
            }
            ull* sc = reinterpret_cast<ull*>(&sm[OFF_SCUR]);
            if (g > 0) {
                #pragma unroll
                for (int c = 0; c < 4; ++c) {
                    ulonglong2 s; s.x = a[c][0]; s.y = a[c][1];
                    *reinterpret_cast<ulonglong2*>(&sc[((g-1)*128 + tl)*8 + c*2]) = s;
                }
            }
            __syncthreads();
            if (g == 0) {
                #pragma unroll
                for (int gg = 0; gg < 3; ++gg)
                    #pragma unroll
                    for (int c = 0; c < 4; ++c) {
                        const ulonglong2 s = *reinterpret_cast<const ulonglong2*>(&sc[(gg*128 + tl)*8 + c*2]);
                        a[c][0] = fadd2(a[c][0], s.x);
                        a[c][1] = fadd2(a[c][1], s.y);
                    }
                const ull ss = pk2(0.08838834764831845f, 0.08838834764831845f);  // 1/sqrt(128)
                #pragma unroll
                for (int c = 0; c < 4; ++c) {
                    *reinterpret_cast<ull*>(&sm[OFF_TMP + (c4+c)*20 + rq*4    ]) = fmul2(a[c][0], ss);
                    *reinterpret_cast<ull*>(&sm[OFF_TMP + (c4+c)*20 + rq*4 + 2]) = fmul2(a[c][1], ss);
                }
            }
        }
        __syncthreads();

        // ---- stage x_v (192 cols) ----
        for (int idx = t; idx < ROWS*192; idx += NTHR) {
            int r = idx / 192, c = idx - r*192;
            sm[OFF_XS + c*20 + r] = xg[(size_t)(r0 + r)*480 + 128 + c];
        }
        __syncthreads();

        // ---- op2: v_k (packed row pairs) -> vk_T stride 18 ----
        {
            int j = t & 63, rg = t >> 6;             // 8 groups of 2 rows
            ull a0 = 0, a1 = 0, a2 = 0;
            const float* W = W_l1 + k*64*64;
            #pragma unroll 8
            for (int i = 0; i < 64; ++i) {
                float w = __ldg(&W[i*64 + j]);
                ull ww = pk2(w, w);
                a0 = ffma2(*reinterpret_cast<const ull*>(&sm[OFF_XS + (i*3 + 0)*20 + rg*2]), ww, a0);
                a1 = ffma2(*reinterpret_cast<const ull*>(&sm[OFF_XS + (i*3 + 1)*20 + rg*2]), ww, a1);
                a2 = ffma2(*reinterpret_cast<const ull*>(&sm[OFF_XS + (i*3 + 2)*20 + rg*2]), ww, a2);
            }
            const ull ei = pk2(0.125f, 0.125f);
            *reinterpret_cast<ull*>(&vkbuf[(j*3 + 0)*18 + rg*2]) = fmul2(a0, ei);
            *reinterpret_cast<ull*>(&vkbuf[(j*3 + 1)*18 + rg*2]) = fmul2(a1, ei);
            *reinterpret_cast<ull*>(&vkbuf[(j*3 + 2)*18 + rg*2]) = fmul2(a2, ei);
        }
        __syncthreads();

        // ---- stage x_T (160 cols) ----
        for (int idx = t; idx < ROWS*160; idx += NTHR) {
            int r = idx / 160, c = idx - r*160;
            sm[OFF_XS + c*20 + r] = xg[(size_t)(r0 + r)*480 + 320 + c];
        }
        __syncthreads();

        // ---- op3 (all threads): n_k into TMP ----
        {
            int j = t & 31, r = t >> 5;
            float a[5] = {};
            const float* W = W_l2 + k*32*32;
            #pragma unroll 8
            for (int i = 0; i < 32; ++i) {
                float w = __ldg(&W[i*32 + j]);
                #pragma unroll
                for (int m = 0; m < 5; ++m) a[m] += sm[OFF_XS + (i*5 + m)*20 + r]*w;
            }
            float s2 = a[0]*a[0] + a[1]*a[1] + a[2]*a[2] + a[3]*a[3] + a[4]*a[4];
            sm[OFF_TMP + (128 + j)*20 + r] = sqrtf(s2)*0.17677669529663687f;  // 1/sqrt(32)
        }

        // ---- op4-GEMM (all threads, packed): U0_T -> VCUR, U1_T -> SCUR ----
        if (k > 0) {
            int j = t & 63, rg = t >> 6;
            ull u0[3] = {}, u1[3] = {};
            #pragma unroll 4
            for (int i = 0; i < 64; ++i) {
                float w0 = __ldg(&W_tp0[i*64 + j]);
                float w1 = __ldg(&W_tp1[i*64 + j]);
                ull ww0 = pk2(w0, w0), ww1 = pk2(w1, w1);
                #pragma unroll
                for (int m = 0; m < 3; ++m) {
                    ull vp = *reinterpret_cast<const ull*>(&vkbuf[(i*3 + m)*18 + rg*2]);
                    u0[m] = ffma2(vp, ww0, u0[m]);
                    u1[m] = ffma2(vp, ww1, u1[m]);
                }
            }
            #pragma unroll
            for (int m = 0; m < 3; ++m) {
                *reinterpret_cast<ull*>(&sm[OFF_VCUR + (j*3 + m)*18 + rg*2]) = u0[m];
                *reinterpret_cast<ull*>(&sm[OFF_SCUR + (j*3 + m)*18 + rg*2]) = u1[m];
            }
        }
        __syncthreads();

        // ---- op4-reduce: p0/p1 per row (warps 0-7, 2 rows/warp) ----
        if (k > 0) {
            int w = t >> 5, lane = t & 31;
            if (w < 8) {
                int ra = 2*w, rb = 2*w + 1;
                float p0a=0,pxa=0,pya=0,pza=0, p0b=0,pxb=0,pyb=0,pzb=0;
                #pragma unroll
                for (int jj = 0; jj < 2; ++jj) {
                    int j = jj*32 + lane;
                    float u00 = sm[OFF_VCUR + (j*3+0)*18 + ra];
                    float u01 = sm[OFF_VCUR + (j*3+1)*18 + ra];
                    float u02 = sm[OFF_VCUR + (j*3+2)*18 + ra];
                    float u10 = sm[OFF_SCUR + (j*3+0)*18 + ra];
                    float u11 = sm[OFF_SCUR + (j*3+1)*18 + ra];
                    float u12 = sm[OFF_SCUR + (j*3+2)*18 + ra];
                    float vx = vpbuf[(j*3+0)*18 + ra];
                    float vy = vpbuf[(j*3+1)*18 + ra];
                    float vz = vpbuf[(j*3+2)*18 + ra];
                    p0a += u00*vx + u01*vy + u02*vz;
                    pxa += u11*vz - u12*vy;
                    pya += u12*vx - u10*vz;
                    pza += u10*vy - u11*vx;
                    u00 = sm[OFF_VCUR + (j*3+0)*18 + rb];
                    u01 = sm[OFF_VCUR + (j*3+1)*18 + rb];
                    u02 = sm[OFF_VCUR + (j*3+2)*18 + rb];
                    u10 = sm[OFF_SCUR + (j*3+0)*18 + rb];
                    u11 = sm[OFF_SCUR + (j*3+1)*18 + rb];
                    u12 = sm[OFF_SCUR + (j*3+2)*18 + rb];
                    vx = vpbuf[(j*3+0)*18 + rb];
                    vy = vpbuf[(j*3+1)*18 + rb];
                    vz = vpbuf[(j*3+2)*18 + rb];
                    p0b += u00*vx + u01*vy + u02*vz;
                    pxb += u11*vz - u12*vy;
                    pyb += u12*vx - u10*vz;
                    pzb += u10*vy - u11*vx;
                }
                #pragma unroll
                for (int off = 16; off > 0; off >>= 1) {
                    p0a += __shfl_down_sync(0xffffffffu, p0a, off);
                    pxa += __shfl_down_sync(0xffffffffu, pxa, off);
                    pya += __shfl_down_sync(0xffffffffu, pya, off);
                    pza += __shfl_down_sync(0xffffffffu, pza, off);
                    p0b += __shfl_down_sync(0xffffffffu, p0b, off);
                    pxb += __shfl_down_sync(0xffffffffu, pxb, off);
                    pyb += __shfl_down_sync(0xffffffffu, pyb, off);
                    pzb += __shfl_down_sync(0xffffffffu, pzb, off);
                }
                if (lane == 0) {
                    const float c0 = 0.009021097956087905f;   // 1/(sqrt(3)*64)
                    const float c1 = 0.011048543456039806f;   // 1/(sqrt(2)*64)
                    sm[OFF_TMP + 160*20 + ra] = p0a*c0;
                    sm[OFF_SP1 + ra*4 + 0] = pxa*c1;
                    sm[OFF_SP1 + ra*4 + 1] = pya*c1;
                    sm[OFF_SP1 + ra*4 + 2] = pza*c1;
                    sm[OFF_TMP + 160*20 + rb] = p0b*c0;
                    sm[OFF_SP1 + rb*4 + 0] = pxb*c1;
                    sm[OFF_SP1 + rb*4 + 1] = pyb*c1;
                    sm[OFF_SP1 + rb*4 + 2] = pzb*c1;
                }
            }
        } else {
            if (t < ROWS) {
                sm[OFF_TMP + 160*20 + t] = 0.f;
                sm[OFF_SP1 + t*4 + 0] = 0.f;
                sm[OFF_SP1 + t*4 + 1] = 0.f;
                sm[OFF_SP1 + t*4 + 2] = 0.f;
            }
        }
        __syncthreads();

        // ---- op5: s_tilde (2 cols x 4 rows per thread, packed) ----
        {
            int c2 = (t & 127) * 2, h4 = t >> 7;     // 4 groups of 4 rows
            ull aA01 = 0, aA23 = 0, aB01 = 0, aB23 = 0;
            const float* W = Ws + k*161*256;
            #pragma unroll 8
            for (int i = 0; i < 160; ++i) {
                const float2 w = *reinterpret_cast<const float2*>(&W[i*256 + c2]);
                ull wx = pk2(w.x, w.x), wy = pk2(w.y, w.y);
                const ulonglong2 xv = *reinterpret_cast<const ulonglong2*>(&sm[OFF_TMP + i*20 + h4*4]);
                aA01 = ffma2(xv.x, wx, aA01);
                aA23 = ffma2(xv.y, wx, aA23);
                aB01 = ffma2(xv.x, wy, aB01);
                aB23 = ffma2(xv.y, wy, aB23);
            }
            {   // i = 160 (p0 column)
                const float2 w = *reinterpret_cast<const float2*>(&W[160*256 + c2]);
                ull wx = pk2(w.x, w.x), wy = pk2(w.y, w.y);
                const ulonglong2 xv = *reinterpret_cast<const ulonglong2*>(&sm[OFF_TMP + 160*20 + h4*4]);
                aA01 = ffma2(xv.x, wx, aA01);
                aA23 = ffma2(xv.y, wx, aA23);
                aB01 = ffma2(xv.x, wy, aB01);
                aB23 = ffma2(xv.y, wy, aB23);
            }
            const float2 bb = *reinterpret_cast<const float2*>(&bs[k*256 + c2]);
            float a0,a1,a2,a3, b0,b1,b2,b3;
            upk2(a0, a1, aA01); upk2(a2, a3, aA23);
            upk2(b0, b1, aB01); upk2(b2, b3, aB23);
            float2 o;
            o.x = a0 + bb.x; o.y = b0 + bb.y;
            *reinterpret_cast<float2*>(&sm[OFF_SCUR + (h4*4 + 0)*256 + c2]) = o;
            o.x = a1 + bb.x; o.y = b1 + bb.y;
            *reinterpret_cast<float2*>(&sm[OFF_SCUR + (h4*4 + 1)*256 + c2]) = o;
            o.x = a2 + bb.x; o.y = b2 + bb.y;
            *reinterpret_cast<float2*>(&sm[OFF_SCUR + (h4*4 + 2)*256 + c2]) = o;
            o.x = a3 + bb.x; o.y = b3 + bb.y;
            *reinterpret_cast<float2*>(&sm[OFF_SCUR + (h4*4 + 3)*256 + c2]) = o;
        }

        // ---- op6: v1o, v1e -> Vcur (row-major) ----
        {
            int j = t & 63, rg = t >> 6;
            ull a0 = 0, a1 = 0, a2 = 0;
            const float* W = Wv1o + k*64*64;
            #pragma unroll 8
            for (int i = 0; i < 64; ++i) {
                float w = __ldg(&W[i*64 + j]);
                ull ww = pk2(w, w);
                a0 = ffma2(*reinterpret_cast<const ull*>(&vkbuf[(i*3 + 0)*18 + rg*2]), ww, a0);
                a1 = ffma2(*reinterpret_cast<const ull*>(&vkbuf[(i*3 + 1)*18 + rg*2]), ww, a1);
                a2 = ffma2(*reinterpret_cast<const ull*>(&vkbuf[(i*3 + 2)*18 + rg*2]), ww, a2);
            }
            float we = __ldg(&Wv1e[k*64 + j]);
            float va0,vb0,va1,vb1,va2,vb2;
            upk2(va0, vb0, a0); upk2(va1, vb1, a1); upk2(va2, vb2, a2);
            int ra = rg*2, rb = rg*2 + 1;
            sm[OFF_VCUR + ra*384 + j*3 + 0] = va0*0.125f;
            sm[OFF_VCUR + ra*384 + j*3 + 1] = va1*0.125f;
            sm[OFF_VCUR + ra*384 + j*3 + 2] = va2*0.125f;
            sm[OFF_VCUR + rb*384 + j*3 + 0] = vb0*0.125f;
            sm[OFF_VCUR + rb*384 + j*3 + 1] = vb1*0.125f;
            sm[OFF_VCUR + rb*384 + j*3 + 2] = vb2*0.125f;
            sm[OFF_VCUR + ra*384 + 192 + j*3 + 0] = sm[OFF_SP1 + ra*4 + 0]*we;
            sm[OFF_VCUR + ra*384 + 192 + j*3 + 1] = sm[OFF_SP1 + ra*4 + 1]*we;
            sm[OFF_VCUR + ra*384 + 192 + j*3 + 2] = sm[OFF_SP1 + ra*4 + 2]*we;
            sm[OFF_VCUR + rb*384 + 192 + j*3 + 0] = sm[OFF_SP1 + rb*4 + 0]*we;
            sm[OFF_VCUR + rb*384 + 192 + j*3 + 1] = sm[OFF_SP1 + rb*4 + 1]*we;
            sm[OFF_VCUR + rb*384 + 192 + j*3 + 2] = sm[OFF_SP1 + rb*4 + 2]*we;
        }
        __syncthreads();

        // ---- layernorm (warp per row) w/ fused m-norms; writes h TRANSPOSED (stride 18) ----
        {
            int r = t >> 5, lane = t & 31;
            float s = 0.f, s2 = 0.f;
            #pragma unroll
            for (int c = lane; c < 384; c += 32) {
                float v;
                if (c < 256) v = sm[OFF_SCUR + r*256 + c];
                else {
                    int idx = c - 256;
                    float a = sm[OFF_VCUR + r*384 + idx*3];
                    float b = sm[OFF_VCUR + r*384 + idx*3 + 1];
                    float d = sm[OFF_VCUR + r*384 + idx*3 + 2];
                    v = sqrtf(a*a + b*b + d*d);
                    sm[OFF_MBUF + r*128 + idx] = v;
                }
                s += v; s2 += v*v;
            }
            #pragma unroll
            for (int off = 16; off > 0; off >>= 1) {
                s  += __shfl_xor_sync(0xffffffffu, s,  off);
                s2 += __shfl_xor_sync(0xffffffffu, s2, off);
            }
            float mu   = s  * (1.f/384.f);
            float var  = s2 * (1.f/384.f) - mu*mu;
            float rstd = rsqrtf(var + 1e-5f);
            #pragma unroll
            for (int c = lane; c < 384; c += 32) {
                float v = (c < 256) ? sm[OFF_SCUR + r*256 + c] : sm[OFF_MBUF + r*128 + c - 256];
                sm[OFF_HBUF + c*18 + r] = (v - mu)*rstd*sm[OFF_GB + c] + sm[OFF_GB + 384 + c];
            }
        }
        // spill S,V (float4, all threads)
        for (int idx = t; idx < ROWS*160; idx += NTHR) {
            int r = idx / 160, q = idx - r*160;
            float4 v;
            if (q < 64) v = *reinterpret_cast<const float4*>(&sm[OFF_SCUR + r*256 + q*4]);
            else        v = *reinterpret_cast<const float4*>(&sm[OFF_VCUR + r*384 + (q - 64)*4]);
            *reinterpret_cast<float4*>(&g_SV[(size_t)(r0 + r)*2560 + (size_t)k*640 + q*4]) = v;
        }
        __syncthreads();

        // ---- MLP: 4 cols x 4 rows per thread, i-split x8, butterfly finish ----
        {
            const int tl = t & 63;
            const int c4 = (tl & 15) * 4;        // 16 colgroups x 4 cols
            const int rg = tl >> 4;              // 4 rowgroups x 4 rows
            const int g  = t >> 6;               // 8 i-chunks of 48
            ull a[4][2] = {};
            const float* Wp = Wm1 + g*48*64;
            #pragma unroll 6
            for (int i = 0; i < 48; ++i) {
                const float4 w4 = *reinterpret_cast<const float4*>(&Wp[i*64 + c4]);
                const ull h0 = *reinterpret_cast<const ull*>(&sm[OFF_HBUF + (g*48 + i)*18 + rg*4]);
                const ull h1 = *reinterpret_cast<const ull*>(&sm[OFF_HBUF + (g*48 + i)*18 + rg*4 + 2]);
                ull ww;
                ww = pk2(w4.x, w4.x); a[0][0]=ffma2(h0,ww,a[0][0]); a[0][1]=ffma2(h1,ww,a[0][1]);
                ww = pk2(w4.y, w4.y); a[1][0]=ffma2(h0,ww,a[1][0]); a[1][1]=ffma2(h1,ww,a[1][1]);
                ww = pk2(w4.z, w4.z); a[2][0]=ffma2(h0,ww,a[2][0]); a[2][1]=ffma2(h1,ww,a[2][1]);
                ww = pk2(w4.w, w4.w); a[3][0]=ffma2(h0,ww,a[3][0]); a[3][1]=ffma2(h1,ww,a[3][1]);
            }
            ull* sc = reinterpret_cast<ull*>(&sm[OFF_SCUR]);
            if (g > 0) {
                #pragma unroll
                for (int c = 0; c < 4; ++c) {
                    ulonglong2 s; s.x = a[c][0]; s.y = a[c][1];
                    *reinterpret_cast<ulonglong2*>(&sc[((g-1)*64 + tl)*8 + c*2]) = s;
                }
            }
            __syncthreads();
            if (g == 0) {
                #pragma unroll
                for (int gg = 0; gg < 7; ++gg)
                    #pragma unroll
                    for (int c = 0; c < 4; ++c) {
                        const ulonglong2 s = *reinterpret_cast<const ulonglong2*>(&sc[(gg*64 + tl)*8 + c*2]);
                        a[c][0] = fadd2(a[c][0], s.x);
                        a[c][1] = fadd2(a[c][1], s.y);
                    }
                float er[4] = {0.f, 0.f, 0.f, 0.f};
                #pragma unroll
                for (int c = 0; c < 4; ++c) {
                    float b1c  = sm[OFF_BM1 + c4 + c];
                    float wm2c = sm[OFF_WM2 + c4 + c];
                    float v0,v1,v2,v3;
                    upk2(v0, v1, a[c][0]); upk2(v2, v3, a[c][1]);
                    float z;
                    z = v0 + b1c; er[0] += z/(1.f + expf(-z))*wm2c;
                    z = v1 + b1c; er[1] += z/(1.f + expf(-z))*wm2c;
                    z = v2 + b1c; er[2] += z/(1.f + expf(-z))*wm2c;
                    z = v3 + b1c; er[3] += z/(1.f + expf(-z))*wm2c;
                }
                #pragma unroll
                for (int m = 8; m >= 1; m >>= 1)
                    #pragma unroll
                    for (int r = 0; r < 4; ++r)
                        er[r] += __shfl_xor_sync(0xffffffffu, er[r], m);
                if ((tl & 15) == 0) {
                    #pragma unroll
                    for (int r = 0; r < 4; ++r)
                        sm[OFF_EV + (rg*4 + r)*4 + k] = er[r];
                }
            }
        }

        { float* tp = vkbuf; vkbuf = vpbuf; vpbuf = tp; }
        __syncthreads();
    }

    // ---- softmax over K (bm2 cancels); alpha written in place into EV ----
    if (t < ROWS) {
        float e0 = sm[OFF_EV + t*4 + 0], e1 = sm[OFF_EV + t*4 + 1];
        float e2 = sm[OFF_EV + t*4 + 2], e3 = sm[OFF_EV + t*4 + 3];
        float mx = fmaxf(fmaxf(e0, e1), fmaxf(e2, e3));
        float z0 = expf(e0 - mx), z1 = expf(e1 - mx), z2 = expf(e2 - mx), z3 = expf(e3 - mx);
        float inv = 1.f/(z0 + z1 + z2 + z3);
        sm[OFF_EV + t*4 + 0] = z0*inv;
        sm[OFF_EV + t*4 + 1] = z1*inv;
        sm[OFF_EV + t*4 + 2] = z2*inv;
        sm[OFF_EV + t*4 + 3] = z3*inv;
    }
    __syncthreads();

    // ---- fused epilogue: out = sum_k alpha_k * SV_k (L2-hot) ----
    for (int idx = t; idx < ROWS*160; idx += NTHR) {
        int r = idx / 160, q = idx - r*160;
        const float* sv = g_SV + (size_t)(r0 + r)*2560 + q*4;
        const float a0 = sm[OFF_EV + r*4 + 0], a1 = sm[OFF_EV + r*4 + 1];
        const float a2 = sm[OFF_EV + r*4 + 2], a3 = sm[OFF_EV + r*4 + 3];
        const float4 v0 = *reinterpret_cast<const float4*>(sv);
        const float4 v1 = *reinterpret_cast<const float4*>(sv + 640);
        const float4 v2 = *reinterpret_cast<const float4*>(sv + 1280);
        const float4 v3 = *reinterpret_cast<const float4*>(sv + 1920);
        float4 o;
        o.x = a0*v0.x + a1*v1.x + a2*v2.x + a3*v3.x;
        o.y = a0*v0.y + a1*v1.y + a2*v2.y + a3*v3.y;
        o.z = a0*v0.z + a1*v1.z + a2*v2.z + a3*v3.z;
        o.w = a0*v0.w + a1*v1.w + a2*v2.w + a3*v3.w;
        if (q < 64) *reinterpret_cast<float4*>(&out[(size_t)(r0 + r)*256 + q*4]) = o;
        else        *reinterpret_cast<float4*>(&out[(size_t)NTOK*256 + (size_t)(r0 + r)*384 + (q - 64)*4]) = o;
    }
}

extern "C" void kernel_launch(void* const* d_in, const int* in_sizes, int n_in,
                              void* d_out, int out_size)
{
    (void)in_sizes; (void)n_in; (void)out_size;
    cudaFuncSetAttribute(fuse_k1, cudaFuncAttributeMaxDynamicSharedMemorySize, SMEM_BYTES);

    fuse_k1<<<NTOK/ROWS, NTHR, SMEM_BYTES>>>(
        (const float*)d_in[0],  (const float*)d_in[1],  (const float*)d_in[2],
        (const float*)d_in[3],  (const float*)d_in[4],  (const float*)d_in[5],
        (const float*)d_in[6],  (const float*)d_in[7],  (const float*)d_in[8],
        (const float*)d_in[9],  (const float*)d_in[10], (const float*)d_in[11],
        (const float*)d_in[12], (const float*)d_in[13], (const float*)d_in[14],
        (const float*)d_in[15], (const float*)d_in[16], (const float*)d_in[17],
        (const float*)d_in[18], (float*)d_out);
}

// round 15
// speedup vs baseline: 1.5806x; 1.1438x over previous
#include <cuda_runtime.h>
#include <math.h>

#define NTOK 80000
#define KK   4
#define ROWS 16
#define NTHR 512

typedef unsigned long long ull;

// ---------------- f32x2 packed helpers ----------------
__device__ __forceinline__ ull pk2(float lo, float hi) {
    ull r;
    asm("mov.b64 %0, {%1, %2};" : "=l"(r) : "r"(__float_as_uint(lo)), "r"(__float_as_uint(hi)));
    return r;
}
__device__ __forceinline__ void upk2(float& lo, float& hi, ull v) {
    unsigned int a, b;
    asm("mov.b64 {%0, %1}, %2;" : "=r"(a), "=r"(b) : "l"(v));
    lo = __uint_as_float(a); hi = __uint_as_float(b);
}
__device__ __forceinline__ ull ffma2(ull a, ull b, ull c) {
    ull d;
    asm("fma.rn.f32x2 %0, %1, %2, %3;" : "=l"(d) : "l"(a), "l"(b), "l"(c));
    return d;
}
__device__ __forceinline__ ull fmul2(ull a, ull b) {
    ull d;
    asm("mul.rn.f32x2 %0, %1, %2;" : "=l"(d) : "l"(a), "l"(b));
    return d;
}
__device__ __forceinline__ ull fadd2(ull a, ull b) {
    ull d;
    asm("add.rn.f32x2 %0, %1, %2;" : "=l"(d) : "l"(a), "l"(b));
    return d;
}

// ---------------- smem layout (float offsets), ~109 KB -> 2 CTAs/SM ----------------
constexpr int OFF_SCUR = 0;                  // 16*256 = 4096 (MLP partial scratch; U1_T in op4)
constexpr int OFF_VCUR = OFF_SCUR + 4096;    // 16*384 = 6144 (U0_T in op4)
constexpr int OFF_XS   = OFF_VCUR + 6144;    // x staging: stride-20 transposed (x_s/x_v) OR split layout (x_T); 3840
constexpr int OFF_TMP  = OFF_XS   + 3840;    // transposed [s_k|n_k|p0], stride 20: 161*20 -> 3232
constexpr int OFF_VKA  = OFF_TMP  + 3232;    // transposed v_k, stride 18: 192*18 = 3456
constexpr int OFF_VKB  = OFF_VKA  + 3456;    // 3456 (dead vpbuf doubles as op5 partial scratch)
constexpr int OFF_MBUF = OFF_VKB  + 3456;    // 16*128 = 2048 (m-norms; op5 scratch overflow)
constexpr int OFF_GB   = OFF_MBUF + 2048;    // gamma 384 + beta 384
constexpr int OFF_BM1  = OFF_GB   + 768;     // 64
constexpr int OFF_WM2  = OFF_BM1  + 64;      // 64
constexpr int OFF_SP1  = OFF_WM2  + 64;      // 16*4
constexpr int OFF_EV   = OFF_SP1  + 64;      // 16*4 (e scores, then alpha)
constexpr int SMEM_FLOATS = OFF_EV + 64;     // 27296 floats
constexpr int SMEM_BYTES  = SMEM_FLOATS * 4; // 109184 B -> 2 blocks/SM
// h_T (transposed LN output, stride 18: 384*18 = 6912) overlays freed XS+TMP (7072)
constexpr int OFF_HBUF = OFF_XS;

// ---------------- global scratch (no allocs allowed) ----------------
__device__ __align__(16) float g_SV[(size_t)NTOK * 2560];  // [row][k][640] : S(256) then V(384)

__global__ void __launch_bounds__(NTHR, 2)
fuse_k1(const float* __restrict__ x0, const float* __restrict__ x1,
        const float* __restrict__ x2, const float* __restrict__ x3,
        const float* __restrict__ W_l0, const float* __restrict__ W_l1,
        const float* __restrict__ W_l2, const float* __restrict__ W_tp0,
        const float* __restrict__ W_tp1, const float* __restrict__ Ws,
        const float* __restrict__ bs, const float* __restrict__ Wv1o,
        const float* __restrict__ Wv1e, const float* __restrict__ gamma,
        const float* __restrict__ beta, const float* __restrict__ Wm1,
        const float* __restrict__ bm1, const float* __restrict__ Wm2,
        const float* __restrict__ bm2, float* __restrict__ out)
{
    extern __shared__ float sm[];
    const int t  = threadIdx.x;
    const int r0 = blockIdx.x * ROWS;

    for (int i = t; i < 384; i += NTHR) { sm[OFF_GB + i] = gamma[i]; sm[OFF_GB + 384 + i] = beta[i]; }
    if (t < 64) { sm[OFF_BM1 + t] = bm1[t]; sm[OFF_WM2 + t] = Wm2[t]; }
    __syncthreads();

    const float* xs_ptr[KK] = {x0, x1, x2, x3};
    float* vkbuf = sm + OFF_VKA;   // transposed [(j*3+m)*18 + r]
    float* vpbuf = sm + OFF_VKB;

    for (int k = 0; k < KK; ++k) {
        const float* xg = xs_ptr[k];

        // ---- stage x_s (transposed, stride 20; conflict-free STS.128 of 4-row columns) ----
        {
            int c = t & 127, rq = t >> 7;
            const float* xp = xg + (size_t)(r0 + rq*4)*480 + c;
            float4 v; v.x = xp[0]; v.y = xp[480]; v.z = xp[960]; v.w = xp[1440];
            *reinterpret_cast<float4*>(&sm[OFF_XS + c*20 + rq*4]) = v;
        }
        __syncthreads();

        // ---- op1: s_k = x_s @ W_l0 * inv0 ; 4 cols x 4 rows per thread, i-split x4 ----
        {
            const int tl = t & 127;
            const int c4 = (tl & 31) * 4;        // 32 colgroups x 4 cols
            const int rq = tl >> 5;              // 4 rowgroups x 4 rows
            const int g  = t >> 7;               // 4 i-chunks of 32
            ull a[4][2] = {};
            const float* W = W_l0 + k*128*128 + g*32*128;
            #pragma unroll 8
            for (int i = 0; i < 32; ++i) {
                const float4 w4 = *reinterpret_cast<const float4*>(&W[i*128 + c4]);
                const ulonglong2 xv = *reinterpret_cast<const ulonglong2*>(&sm[OFF_XS + (g*32 + i)*20 + rq*4]);
                ull ww;
                ww = pk2(w4.x, w4.x); a[0][0]=ffma2(xv.x,ww,a[0][0]); a[0][1]=ffma2(xv.y,ww,a[0][1]);
                ww = pk2(w4.y, w4.y); a[1][0]=ffma2(xv.x,ww,a[1][0]); a[1][1]=ffma2(xv.y,ww,a[1][1]);
                ww = pk2(w4.z, w4.z); a[2][0]=ffma2(xv.x,ww,a[2][0]); a[2][1]=ffma2(xv.y,ww,a[2][1]);
                ww = pk2(w4.w, w4.w); a[3][0]=ffma2(xv.x,ww,a[3][0]); a[3][1]=ffma2(xv.y,ww,a[3][1]);
            }
            ull* sc = reinterpret_cast<ull*>(&sm[OFF_SCUR]);
            if (g > 0) {
                #pragma unroll
                for (int c = 0; c < 4; ++c) {
                    ulonglong2 s; s.x = a[c][0]; s.y = a[c][1];
                    *reinterpret_cast<ulonglong2*>(&sc[((g-1)*128 + tl)*8 + c*2]) = s;
                }
            }
            __syncthreads();
            if (g == 0) {
                #pragma unroll
                for (int gg = 0; gg < 3; ++gg)
                    #pragma unroll
                    for (int c = 0; c < 4; ++c) {
                        const ulonglong2 s = *reinterpret_cast<const ulonglong2*>(&sc[(gg*128 + tl)*8 + c*2]);
                        a[c][0] = fadd2(a[c][0], s.x);
                        a[c][1] = fadd2(a[c][1], s.y);
                    }
                const ull ss = pk2(0.08838834764831845f, 0.08838834764831845f);  // 1/sqrt(128)
                #pragma unroll
                for (int c = 0; c < 4; ++c) {
                    *reinterpret_cast<ull*>(&sm[OFF_TMP + (c4+c)*20 + rq*4    ]) = fmul2(a[c][0], ss);
                    *reinterpret_cast<ull*>(&sm[OFF_TMP + (c4+c)*20 + rq*4 + 2]) = fmul2(a[c][1], ss);
                }
            }
        }
        __syncthreads();

        // ---- stage x_v (192 cols, transposed stride 20, STS.128) ----
        for (int u = t; u < 192*4; u += NTHR) {
            int c = u % 192, rq = u / 192;
            const float* xp = xg + (size_t)(r0 + rq*4)*480 + 128 + c;
            float4 v; v.x = xp[0]; v.y = xp[480]; v.z = xp[960]; v.w = xp[1440];
            *reinterpret_cast<float4*>(&sm[OFF_XS + c*20 + rq*4]) = v;
        }
        __syncthreads();

        // ---- op2: v_k (packed row pairs) -> vk_T stride 18 ----
        {
            int j = t & 63, rg = t >> 6;             // 8 groups of 2 rows
            ull a0 = 0, a1 = 0, a2 = 0;
            const float* W = W_l1 + k*64*64;
            #pragma unroll 8
            for (int i = 0; i < 64; ++i) {
                float w = __ldg(&W[i*64 + j]);
                ull ww = pk2(w, w);
                a0 = ffma2(*reinterpret_cast<const ull*>(&sm[OFF_XS + (i*3 + 0)*20 + rg*2]), ww, a0);
                a1 = ffma2(*reinterpret_cast<const ull*>(&sm[OFF_XS + (i*3 + 1)*20 + rg*2]), ww, a1);
                a2 = ffma2(*reinterpret_cast<const ull*>(&sm[OFF_XS + (i*3 + 2)*20 + rg*2]), ww, a2);
            }
            const ull ei = pk2(0.125f, 0.125f);
            *reinterpret_cast<ull*>(&vkbuf[(j*3 + 0)*18 + rg*2]) = fmul2(a0, ei);
            *reinterpret_cast<ull*>(&vkbuf[(j*3 + 1)*18 + rg*2]) = fmul2(a1, ei);
            *reinterpret_cast<ull*>(&vkbuf[(j*3 + 2)*18 + rg*2]) = fmul2(a2, ei);
        }
        __syncthreads();

        // ---- stage x_T in split layout: [r][i][m0..3] (float4-aligned) + scalar plane [r][i] ----
        for (int u = t; u < ROWS*160; u += NTHR) {
            int r = u / 160, c = u - r*160;
            int i = c / 5, m = c - i*5;
            float v = xg[(size_t)(r0 + r)*480 + 320 + c];
            if (m < 4) sm[OFF_XS + r*128 + i*4 + m] = v;
            else       sm[OFF_XS + 2048 + r*32 + i] = v;
        }
        __syncthreads();

        // ---- op3 (all threads): n_k into TMP (1 LDS.128 + 1 LDS.32 per iter) ----
        {
            int j = t & 31, r = t >> 5;
            float a[5] = {};
            const float* W = W_l2 + k*32*32;
            const float* xr4 = &sm[OFF_XS + r*128];
            const float* xr1 = &sm[OFF_XS + 2048 + r*32];
            #pragma unroll 8
            for (int i = 0; i < 32; ++i) {
                float w = __ldg(&W[i*32 + j]);
                const float4 xv = *reinterpret_cast<const float4*>(&xr4[i*4]);
                float xe = xr1[i];
                a[0] += xv.x*w; a[1] += xv.y*w; a[2] += xv.z*w; a[3] += xv.w*w; a[4] += xe*w;
            }
            float s2 = a[0]*a[0] + a[1]*a[1] + a[2]*a[2] + a[3]*a[3] + a[4]*a[4];
            sm[OFF_TMP + (128 + j)*20 + r] = sqrtf(s2)*0.17677669529663687f;  // 1/sqrt(32)
        }

        // ---- op4-GEMM (all threads, packed): U0_T -> VCUR, U1_T -> SCUR ----
        if (k > 0) {
            int j = t & 63, rg = t >> 6;
            ull u0[3] = {}, u1[3] = {};
            #pragma unroll 4
            for (int i = 0; i < 64; ++i) {
                float w0 = __ldg(&W_tp0[i*64 + j]);
                float w1 = __ldg(&W_tp1[i*64 + j]);
                ull ww0 = pk2(w0, w0), ww1 = pk2(w1, w1);
                #pragma unroll
                for (int m = 0; m < 3; ++m) {
                    ull vp = *reinterpret_cast<const ull*>(&vkbuf[(i*3 + m)*18 + rg*2]);
                    u0[m] = ffma2(vp, ww0, u0[m]);
                    u1[m] = ffma2(vp, ww1, u1[m]);
                }
            }
            #pragma unroll
            for (int m = 0; m < 3; ++m) {
                *reinterpret_cast<ull*>(&sm[OFF_VCUR + (j*3 + m)*18 + rg*2]) = u0[m];
                *reinterpret_cast<ull*>(&sm[OFF_SCUR + (j*3 + m)*18 + rg*2]) = u1[m];
            }
        }
        __syncthreads();

        // ---- op4-reduce: p0/p1 per row (warps 0-7, 2 rows/warp) ----
        if (k > 0) {
            int w = t >> 5, lane = t & 31;
            if (w < 8) {
                int ra = 2*w, rb = 2*w + 1;
                float p0a=0,pxa=0,pya=0,pza=0, p0b=0,pxb=0,pyb=0,pzb=0;
                #pragma unroll
                for (int jj = 0; jj < 2; ++jj) {
                    int j = jj*32 + lane;
                    float u00 = sm[OFF_VCUR + (j*3+0)*18 + ra];
                    float u01 = sm[OFF_VCUR + (j*3+1)*18 + ra];
                    float u02 = sm[OFF_VCUR + (j*3+2)*18 + ra];
                    float u10 = sm[OFF_SCUR + (j*3+0)*18 + ra];
                    float u11 = sm[OFF_SCUR + (j*3+1)*18 + ra];
                    float u12 = sm[OFF_SCUR + (j*3+2)*18 + ra];
                    float vx = vpbuf[(j*3+0)*18 + ra];
                    float vy = vpbuf[(j*3+1)*18 + ra];
                    float vz = vpbuf[(j*3+2)*18 + ra];
                    p0a += u00*vx + u01*vy + u02*vz;
                    pxa += u11*vz - u12*vy;
                    pya += u12*vx - u10*vz;
                    pza += u10*vy - u11*vx;
                    u00 = sm[OFF_VCUR + (j*3+0)*18 + rb];
                    u01 = sm[OFF_VCUR + (j*3+1)*18 + rb];
                    u02 = sm[OFF_VCUR + (j*3+2)*18 + rb];
                    u10 = sm[OFF_SCUR + (j*3+0)*18 + rb];
                    u11 = sm[OFF_SCUR + (j*3+1)*18 + rb];
                    u12 = sm[OFF_SCUR + (j*3+2)*18 + rb];
                    vx = vpbuf[(j*3+0)*18 + rb];
                    vy = vpbuf[(j*3+1)*18 + rb];
                    vz = vpbuf[(j*3+2)*18 + rb];
                    p0b += u00*vx + u01*vy + u02*vz;
                    pxb += u11*vz - u12*vy;
                    pyb += u12*vx - u10*vz;
                    pzb += u10*vy - u11*vx;
                }
                #pragma unroll
                for (int off = 16; off > 0; off >>= 1) {
                    p0a += __shfl_down_sync(0xffffffffu, p0a, off);
                    pxa += __shfl_down_sync(0xffffffffu, pxa, off);
                    pya += __shfl_down_sync(0xffffffffu, pya, off);
                    pza += __shfl_down_sync(0xffffffffu, pza, off);
                    p0b += __shfl_down_sync(0xffffffffu, p0b, off);
                    pxb += __shfl_down_sync(0xffffffffu, pxb, off);
                    pyb += __shfl_down_sync(0xffffffffu, pyb, off);
                    pzb += __shfl_down_sync(0xffffffffu, pzb, off);
                }
                if (lane == 0) {
                    const float c0 = 0.009021097956087905f;   // 1/(sqrt(3)*64)
                    const float c1 = 0.011048543456039806f;   // 1/(sqrt(2)*64)
                    sm[OFF_TMP + 160*20 + ra] = p0a*c0;
                    sm[OFF_SP1 + ra*4 + 0] = pxa*c1;
                    sm[OFF_SP1 + ra*4 + 1] = pya*c1;
                    sm[OFF_SP1 + ra*4 + 2] = pza*c1;
                    sm[OFF_TMP + 160*20 + rb] = p0b*c0;
                    sm[OFF_SP1 + rb*4 + 0] = pxb*c1;
                    sm[OFF_SP1 + rb*4 + 1] = pyb*c1;
                    sm[OFF_SP1 + rb*4 + 2] = pzb*c1;
                }
            }
        } else {
            if (t < ROWS) {
                sm[OFF_TMP + 160*20 + t] = 0.f;
                sm[OFF_SP1 + t*4 + 0] = 0.f;
                sm[OFF_SP1 + t*4 + 1] = 0.f;
                sm[OFF_SP1 + t*4 + 2] = 0.f;
            }
        }
        __syncthreads();

        // ---- op5: s_tilde; 2 cols x 8 rows per thread, i-split x2 (partials in vpbuf+MBUF) ----
        // ---- then {op5-combine | op6} split across thread halves ----
        {
            const int tl = t & 255;
            const int c2 = (tl & 127) * 2;       // 128 colgroups x 2 cols
            const int rh8 = (tl >> 7) * 8;       // 2 rowgroups x 8 rows
            const int g = t >> 8;                // i-split halves
            const int ibeg = g ? 81 : 0;
            const int iend = g ? 161 : 81;
            ull aA[4] = {}, aB[4] = {};
            const float* W = Ws + k*161*256;
            #pragma unroll 8
            for (int i = ibeg; i < iend; ++i) {
                const float2 w = *reinterpret_cast<const float2*>(&W[i*256 + c2]);
                ull wx = pk2(w.x, w.x), wy = pk2(w.y, w.y);
                const ulonglong2 xa = *reinterpret_cast<const ulonglong2*>(&sm[OFF_TMP + i*20 + rh8]);
                const ulonglong2 xb = *reinterpret_cast<const ulonglong2*>(&sm[OFF_TMP + i*20 + rh8 + 4]);
                aA[0] = ffma2(xa.x, wx, aA[0]);
                aA[1] = ffma2(xa.y, wx, aA[1]);
                aA[2] = ffma2(xb.x, wx, aA[2]);
                aA[3] = ffma2(xb.y, wx, aA[3]);
                aB[0] = ffma2(xa.x, wy, aB[0]);
                aB[1] = ffma2(xa.y, wy, aB[1]);
                aB[2] = ffma2(xb.x, wy, aB[2]);
                aB[3] = ffma2(xb.y, wy, aB[3]);
            }
            float* scr = (tl < 216) ? (vpbuf + tl*16) : (sm + OFF_MBUF + (tl - 216)*16);
            if (g == 1) {
                ulonglong2 s;
                s.x = aA[0]; s.y = aA[1]; *reinterpret_cast<ulonglong2*>(scr + 0) = s;
                s.x = aA[2]; s.y = aA[3]; *reinterpret_cast<ulonglong2*>(scr + 4) = s;
                s.x = aB[0]; s.y = aB[1]; *reinterpret_cast<ulonglong2*>(scr + 8) = s;
                s.x = aB[2]; s.y = aB[3]; *reinterpret_cast<ulonglong2*>(scr + 12) = s;
            }
            __syncthreads();
            if (g == 0) {
                ulonglong2 s;
                s = *reinterpret_cast<const ulonglong2*>(scr + 0);
                aA[0] = fadd2(aA[0], s.x); aA[1] = fadd2(aA[1], s.y);
                s = *reinterpret_cast<const ulonglong2*>(scr + 4);
                aA[2] = fadd2(aA[2], s.x); aA[3] = fadd2(aA[3], s.y);
                s = *reinterpret_cast<const ulonglong2*>(scr + 8);
                aB[0] = fadd2(aB[0], s.x); aB[1] = fadd2(aB[1], s.y);
                s = *reinterpret_cast<const ulonglong2*>(scr + 12);
                aB[2] = fadd2(aB[2], s.x); aB[3] = fadd2(aB[3], s.y);
                const float2 bb = *reinterpret_cast<const float2*>(&bs[k*256 + c2]);
                #pragma unroll
                for (int q = 0; q < 4; ++q) {
                    float alo, ahi, blo, bhi;
                    upk2(alo, ahi, aA[q]); upk2(blo, bhi, aB[q]);
                    float2 o;
                    o.x = alo + bb.x; o.y = blo + bb.y;
                    *reinterpret_cast<float2*>(&sm[OFF_SCUR + (rh8 + q*2    )*256 + c2]) = o;
                    o.x = ahi + bb.x; o.y = bhi + bb.y;
                    *reinterpret_cast<float2*>(&sm[OFF_SCUR + (rh8 + q*2 + 1)*256 + c2]) = o;
                }
            } else {
                // ---- op6 on threads 256-511: 64 cols x 4 rows/thread ----
                const int tl2 = t - 256;
                const int j = tl2 & 63, rg = tl2 >> 6;   // 4 rowgroups x 4 rows
                ull a0l=0,a0h=0, a1l=0,a1h=0, a2l=0,a2h=0;
                const float* W6 = Wv1o + k*64*64;
                #pragma unroll 8
                for (int i = 0; i < 64; ++i) {
                    float w = __ldg(&W6[i*64 + j]);
                    ull ww = pk2(w, w);
                    a0l = ffma2(*reinterpret_cast<const ull*>(&vkbuf[(i*3 + 0)*18 + rg*4    ]), ww, a0l);
                    a0h = ffma2(*reinterpret_cast<const ull*>(&vkbuf[(i*3 + 0)*18 + rg*4 + 2]), ww, a0h);
                    a1l = ffma2(*reinterpret_cast<const ull*>(&vkbuf[(i*3 + 1)*18 + rg*4    ]), ww, a1l);
                    a1h = ffma2(*reinterpret_cast<const ull*>(&vkbuf[(i*3 + 1)*18 + rg*4 + 2]), ww, a1h);
                    a2l = ffma2(*reinterpret_cast<const ull*>(&vkbuf[(i*3 + 2)*18 + rg*4    ]), ww, a2l);
                    a2h = ffma2(*reinterpret_cast<const ull*>(&vkbuf[(i*3 + 2)*18 + rg*4 + 2]), ww, a2h);
                }
                float we = __ldg(&Wv1e[k*64 + j]);
                float f0[4], f1[4], f2[4];
                upk2(f0[0], f0[1], a0l); upk2(f0[2], f0[3], a0h);
                upk2(f1[0], f1[1], a1l); upk2(f1[2], f1[3], a1h);
                upk2(f2[0], f2[1], a2l); upk2(f2[2], f2[3], a2h);
                #pragma unroll
                for (int rr = 0; rr < 4; ++rr) {
                    int r = rg*4 + rr;
                    sm[OFF_VCUR + r*384 + j*3 + 0] = f0[rr]*0.125f;
                    sm[OFF_VCUR + r*384 + j*3 + 1] = f1[rr]*0.125f;
                    sm[OFF_VCUR + r*384 + j*3 + 2] = f2[rr]*0.125f;
                    sm[OFF_VCUR + r*384 + 192 + j*3 + 0] = sm[OFF_SP1 + r*4 + 0]*we;
                    sm[OFF_VCUR + r*384 + 192 + j*3 + 1] = sm[OFF_SP1 + r*4 + 1]*we;
                    sm[OFF_VCUR + r*384 + 192 + j*3 + 2] = sm[OFF_SP1 + r*4 + 2]*we;
                }
            }
        }
        __syncthreads();

        // ---- layernorm (warp per row) w/ fused m-norms; writes h TRANSPOSED (stride 18) ----
        {
            int r = t >> 5, lane = t & 31;
            float s = 0.f, s2 = 0.f;
            #pragma unroll
            for (int c = lane; c < 384; c += 32) {
                float v;
                if (c < 256) v = sm[OFF_SCUR + r*256 + c];
                else {
                    int idx = c - 256;
                    float a = sm[OFF_VCUR + r*384 + idx*3];
                    float b = sm[OFF_VCUR + r*384 + idx*3 + 1];
                    float d = sm[OFF_VCUR + r*384 + idx*3 + 2];
                    v = sqrtf(a*a + b*b + d*d);
                    sm[OFF_MBUF + r*128 + idx] = v;
                }
                s += v; s2 += v*v;
            }
            #pragma unroll
            for (int off = 16; off > 0; off >>= 1) {
                s  += __shfl_xor_sync(0xffffffffu, s,  off);
                s2 += __shfl_xor_sync(0xffffffffu, s2, off);
            }
            float mu   = s  * (1.f/384.f);
            float var  = s2 * (1.f/384.f) - mu*mu;
            float rstd = rsqrtf(var + 1e-5f);
            #pragma unroll
            for (int c = lane; c < 384; c += 32) {
                float v = (c < 256) ? sm[OFF_SCUR + r*256 + c] : sm[OFF_MBUF + r*128 + c - 256];
                sm[OFF_HBUF + c*18 + r] = (v - mu)*rstd*sm[OFF_GB + c] + sm[OFF_GB + 384 + c];
            }
        }
        // spill S,V (float4, all threads)
        for (int idx = t; idx < ROWS*160; idx += NTHR) {
            int r = idx / 160, q = idx - r*160;
            float4 v;
            if (q < 64) v = *reinterpret_cast<const float4*>(&sm[OFF_SCUR + r*256 + q*4]);
            else        v = *reinterpret_cast<const float4*>(&sm[OFF_VCUR + r*384 + (q - 64)*4]);
            *reinterpret_cast<float4*>(&g_SV[(size_t)(r0 + r)*2560 + (size_t)k*640 + q*4]) = v;
        }
        __syncthreads();

        // ---- MLP: 4 cols x 4 rows per thread, i-split x8, butterfly finish ----
        {
            const int tl = t & 63;
            const int c4 = (tl & 15) * 4;        // 16 colgroups x 4 cols
            const int rg = tl >> 4;              // 4 rowgroups x 4 rows
            const int g  = t >> 6;               // 8 i-chunks of 48
            ull a[4][2] = {};
            const float* Wp = Wm1 + g*48*64;
            #pragma unroll 6
            for (int i = 0; i < 48; ++i) {
                const float4 w4 = *reinterpret_cast<const float4*>(&Wp[i*64 + c4]);
                const ull h0 = *reinterpret_cast<const ull*>(&sm[OFF_HBUF + (g*48 + i)*18 + rg*4]);
                const ull h1 = *reinterpret_cast<const ull*>(&sm[OFF_HBUF + (g*48 + i)*18 + rg*4 + 2]);
                ull ww;
                ww = pk2(w4.x, w4.x); a[0][0]=ffma2(h0,ww,a[0][0]); a[0][1]=ffma2(h1,ww,a[0][1]);
                ww = pk2(w4.y, w4.y); a[1][0]=ffma2(h0,ww,a[1][0]); a[1][1]=ffma2(h1,ww,a[1][1]);
                ww = pk2(w4.z, w4.z); a[2][0]=ffma2(h0,ww,a[2][0]); a[2][1]=ffma2(h1,ww,a[2][1]);
                ww = pk2(w4.w, w4.w); a[3][0]=ffma2(h0,ww,a[3][0]); a[3][1]=ffma2(h1,ww,a[3][1]);
            }
            ull* sc = reinterpret_cast<ull*>(&sm[OFF_SCUR]);
            if (g > 0) {
                #pragma unroll
                for (int c = 0; c < 4; ++c) {
                    ulonglong2 s; s.x = a[c][0]; s.y = a[c][1];
                    *reinterpret_cast<ulonglong2*>(&sc[((g-1)*64 + tl)*8 + c*2]) = s;
                }
            }
            __syncthreads();
            if (g == 0) {
                #pragma unroll
                for (int gg = 0; gg < 7; ++gg)
                    #pragma unroll
                    for (int c = 0; c < 4; ++c) {
                        const ulonglong2 s = *reinterpret_cast<const ulonglong2*>(&sc[(gg*64 + tl)*8 + c*2]);
                        a[c][0] = fadd2(a[c][0], s.x);
                        a[c][1] = fadd2(a[c][1], s.y);
                    }
                float er[4] = {0.f, 0.f, 0.f, 0.f};
                #pragma unroll
                for (int c = 0; c < 4; ++c) {
                    float b1c  = sm[OFF_BM1 + c4 + c];
                    float wm2c = sm[OFF_WM2 + c4 + c];
                    float v0,v1,v2,v3;
                    upk2(v0, v1, a[c][0]); upk2(v2, v3, a[c][1]);
                    float z;
                    z = v0 + b1c; er[0] += z/(1.f + expf(-z))*wm2c;
                    z = v1 + b1c; er[1] += z/(1.f + expf(-z))*wm2c;
                    z = v2 + b1c; er[2] += z/(1.f + expf(-z))*wm2c;
                    z = v3 + b1c; er[3] += z/(1.f + expf(-z))*wm2c;
                }
                #pragma unroll
                for (int m = 8; m >= 1; m >>= 1)
                    #pragma unroll
                    for (int r = 0; r < 4; ++r)
                        er[r] += __shfl_xor_sync(0xffffffffu, er[r], m);
                if ((tl & 15) == 0) {
                    #pragma unroll
                    for (int r = 0; r < 4; ++r)
                        sm[OFF_EV + (rg*4 + r)*4 + k] = er[r];
                }
            }
        }

        { float* tp = vkbuf; vkbuf = vpbuf; vpbuf = tp; }
        __syncthreads();
    }

    // ---- softmax over K (bm2 cancels); alpha written in place into EV ----
    if (t < ROWS) {
        float e0 = sm[OFF_EV + t*4 + 0], e1 = sm[OFF_EV + t*4 + 1];
        float e2 = sm[OFF_EV + t*4 + 2], e3 = sm[OFF_EV + t*4 + 3];
        float mx = fmaxf(fmaxf(e0, e1), fmaxf(e2, e3));
        float z0 = expf(e0 - mx), z1 = expf(e1 - mx), z2 = expf(e2 - mx), z3 = expf(e3 - mx);
        float inv = 1.f/(z0 + z1 + z2 + z3);
        sm[OFF_EV + t*4 + 0] = z0*inv;
        sm[OFF_EV + t*4 + 1] = z1*inv;
        sm[OFF_EV + t*4 + 2] = z2*inv;
        sm[OFF_EV + t*4 + 3] = z3*inv;
    }
    __syncthreads();

    // ---- fused epilogue: out = sum_k alpha_k * SV_k (L2-hot) ----
    for (int idx = t; idx < ROWS*160; idx += NTHR) {
        int r = idx / 160, q = idx - r*160;
        const float* sv = g_SV + (size_t)(r0 + r)*2560 + q*4;
        const float a0 = sm[OFF_EV + r*4 + 0], a1 = sm[OFF_EV + r*4 + 1];
        const float a2 = sm[OFF_EV + r*4 + 2], a3 = sm[OFF_EV + r*4 + 3];
        const float4 v0 = *reinterpret_cast<const float4*>(sv);
        const float4 v1 = *reinterpret_cast<const float4*>(sv + 640);
        const float4 v2 = *reinterpret_cast<const float4*>(sv + 1280);
        const float4 v3 = *reinterpret_cast<const float4*>(sv + 1920);
        float4 o;
        o.x = a0*v0.x + a1*v1.x + a2*v2.x + a3*v3.x;
        o.y = a0*v0.y + a1*v1.y + a2*v2.y + a3*v3.y;
        o.z = a0*v0.z + a1*v1.z + a2*v2.z + a3*v3.z;
        o.w = a0*v0.w + a1*v1.w + a2*v2.w + a3*v3.w;
        if (q < 64) *reinterpret_cast<float4*>(&out[(size_t)(r0 + r)*256 + q*4]) = o;
        else        *reinterpret_cast<float4*>(&out[(size_t)NTOK*256 + (size_t)(r0 + r)*384 + (q - 64)*4]) = o;
    }
}

extern "C" void kernel_launch(void* const* d_in, const int* in_sizes, int n_in,
                              void* d_out, int out_size)
{
    (void)in_sizes; (void)n_in; (void)out_size;
    cudaFuncSetAttribute(fuse_k1, cudaFuncAttributeMaxDynamicSharedMemorySize, SMEM_BYTES);

    fuse_k1<<<NTOK/ROWS, NTHR, SMEM_BYTES>>>(
        (const float*)d_in[0],  (const float*)d_in[1],  (const float*)d_in[2],
        (const float*)d_in[3],  (const float*)d_in[4],  (const float*)d_in[5],
        (const float*)d_in[6],  (const float*)d_in[7],  (const float*)d_in[8],
        (const float*)d_in[9],  (const float*)d_in[10], (const float*)d_in[11],
        (const float*)d_in[12], (const float*)d_in[13], (const float*)d_in[14],
        (const float*)d_in[15], (const float*)d_in[16], (const float*)d_in[17],
        (const float*)d_in[18], (float*)d_out);
}

// round 16
// speedup vs baseline: 1.7757x; 1.1234x over previous
#include <cuda_runtime.h>
#include <math.h>

#define NTOK 80000
#define KK   4
#define ROWS 16
#define NTHR 512

typedef unsigned long long ull;

// ---------------- f32x2 packed helpers ----------------
__device__ __forceinline__ ull pk2(float lo, float hi) {
    ull r;
    asm("mov.b64 %0, {%1, %2};" : "=l"(r) : "r"(__float_as_uint(lo)), "r"(__float_as_uint(hi)));
    return r;
}
__device__ __forceinline__ void upk2(float& lo, float& hi, ull v) {
    unsigned int a, b;
    asm("mov.b64 {%0, %1}, %2;" : "=r"(a), "=r"(b) : "l"(v));
    lo = __uint_as_float(a); hi = __uint_as_float(b);
}
__device__ __forceinline__ ull ffma2(ull a, ull b, ull c) {
    ull d;
    asm("fma.rn.f32x2 %0, %1, %2, %3;" : "=l"(d) : "l"(a), "l"(b), "l"(c));
    return d;
}
__device__ __forceinline__ ull fmul2(ull a, ull b) {
    ull d;
    asm("mul.rn.f32x2 %0, %1, %2;" : "=l"(d) : "l"(a), "l"(b));
    return d;
}
__device__ __forceinline__ ull fadd2(ull a, ull b) {
    ull d;
    asm("add.rn.f32x2 %0, %1, %2;" : "=l"(d) : "l"(a), "l"(b));
    return d;
}

// ---------------- smem layout (float offsets), ~109 KB -> 2 CTAs/SM ----------------
constexpr int OFF_SCUR = 0;                  // 16*256 = 4096 (scratch; U1_T in op4)
constexpr int OFF_VCUR = OFF_SCUR + 4096;    // 16*384 = 6144 (scratch; U0_T in op4)
constexpr int OFF_XS   = OFF_VCUR + 6144;    // x staging; 3840
constexpr int OFF_TMP  = OFF_XS   + 3840;    // transposed [s_k|n_k|p0], stride 20: 3232
constexpr int OFF_VKA  = OFF_TMP  + 3232;    // transposed v_k, stride 18: 3456
constexpr int OFF_VKB  = OFF_VKA  + 3456;    // 3456 (dead vpbuf doubles as op5 partial scratch)
constexpr int OFF_MBUF = OFF_VKB  + 3456;    // 2048 (m-norms; op5 scratch overflow)
constexpr int OFF_GB   = OFF_MBUF + 2048;    // gamma 384 + beta 384
constexpr int OFF_BM1  = OFF_GB   + 768;     // 64
constexpr int OFF_WM2  = OFF_BM1  + 64;      // 64
constexpr int OFF_SP1  = OFF_WM2  + 64;      // 16*4
constexpr int OFF_EV   = OFF_SP1  + 64;      // 16*4 (e scores, then alpha)
constexpr int SMEM_FLOATS = OFF_EV + 64;     // 27296 floats
constexpr int SMEM_BYTES  = SMEM_FLOATS * 4; // 109184 B -> 2 blocks/SM
constexpr int OFF_HBUF = OFF_XS;             // h_T stride 18 overlays XS+TMP

// ---------------- global scratch (no allocs allowed) ----------------
__device__ __align__(16) float g_SV[(size_t)NTOK * 2560];  // [row][k][640]

__global__ void __launch_bounds__(NTHR, 2)
fuse_k1(const float* __restrict__ x0, const float* __restrict__ x1,
        const float* __restrict__ x2, const float* __restrict__ x3,
        const float* __restrict__ W_l0, const float* __restrict__ W_l1,
        const float* __restrict__ W_l2, const float* __restrict__ W_tp0,
        const float* __restrict__ W_tp1, const float* __restrict__ Ws,
        const float* __restrict__ bs, const float* __restrict__ Wv1o,
        const float* __restrict__ Wv1e, const float* __restrict__ gamma,
        const float* __restrict__ beta, const float* __restrict__ Wm1,
        const float* __restrict__ bm1, const float* __restrict__ Wm2,
        const float* __restrict__ bm2, float* __restrict__ out)
{
    extern __shared__ float sm[];
    const int t  = threadIdx.x;
    const int r0 = blockIdx.x * ROWS;

    for (int i = t; i < 384; i += NTHR) { sm[OFF_GB + i] = gamma[i]; sm[OFF_GB + 384 + i] = beta[i]; }
    if (t < 64) { sm[OFF_BM1 + t] = bm1[t]; sm[OFF_WM2 + t] = Wm2[t]; }
    __syncthreads();

    const float* xs_ptr[KK] = {x0, x1, x2, x3};
    float* vkbuf = sm + OFF_VKA;   // transposed [(j*3+m)*18 + r]
    float* vpbuf = sm + OFF_VKB;

    for (int k = 0; k < KK; ++k) {
        const float* xg = xs_ptr[k];

        // ---- stage x_s (transposed, stride 20; STS.128 of 4-row columns) ----
        {
            int c = t & 127, rq = t >> 7;
            const float* xp = xg + (size_t)(r0 + rq*4)*480 + c;
            float4 v; v.x = xp[0]; v.y = xp[480]; v.z = xp[960]; v.w = xp[1440];
            *reinterpret_cast<float4*>(&sm[OFF_XS + c*20 + rq*4]) = v;
        }
        __syncthreads();

        // ---- op1: s_k = x_s @ W_l0 * inv0 ; 4 cols x 4 rows, i-split x4 (coalesced combine) ----
        {
            const int tl = t & 127;
            const int c4 = (tl & 31) * 4;
            const int rq = tl >> 5;
            const int g  = t >> 7;
            ull a[4][2] = {};
            const float* W = W_l0 + k*128*128 + g*32*128;
            #pragma unroll 8
            for (int i = 0; i < 32; ++i) {
                const float4 w4 = *reinterpret_cast<const float4*>(&W[i*128 + c4]);
                const ulonglong2 xv = *reinterpret_cast<const ulonglong2*>(&sm[OFF_XS + (g*32 + i)*20 + rq*4]);
                ull ww;
                ww = pk2(w4.x, w4.x); a[0][0]=ffma2(xv.x,ww,a[0][0]); a[0][1]=ffma2(xv.y,ww,a[0][1]);
                ww = pk2(w4.y, w4.y); a[1][0]=ffma2(xv.x,ww,a[1][0]); a[1][1]=ffma2(xv.y,ww,a[1][1]);
                ww = pk2(w4.z, w4.z); a[2][0]=ffma2(xv.x,ww,a[2][0]); a[2][1]=ffma2(xv.y,ww,a[2][1]);
                ww = pk2(w4.w, w4.w); a[3][0]=ffma2(xv.x,ww,a[3][0]); a[3][1]=ffma2(xv.y,ww,a[3][1]);
            }
            ull* sc = reinterpret_cast<ull*>(&sm[OFF_SCUR]);
            if (g > 0) {
                #pragma unroll
                for (int c = 0; c < 4; ++c) {
                    ulonglong2 s; s.x = a[c][0]; s.y = a[c][1];
                    *reinterpret_cast<ulonglong2*>(&sc[(c*384 + (g-1)*128 + tl)*2]) = s;
                }
            }
            __syncthreads();
            if (g == 0) {
                #pragma unroll
                for (int gg = 0; gg < 3; ++gg)
                    #pragma unroll
                    for (int c = 0; c < 4; ++c) {
                        const ulonglong2 s = *reinterpret_cast<const ulonglong2*>(&sc[(c*384 + gg*128 + tl)*2]);
                        a[c][0] = fadd2(a[c][0], s.x);
                        a[c][1] = fadd2(a[c][1], s.y);
                    }
                const ull ss = pk2(0.08838834764831845f, 0.08838834764831845f);
                #pragma unroll
                for (int c = 0; c < 4; ++c) {
                    *reinterpret_cast<ull*>(&sm[OFF_TMP + (c4+c)*20 + rq*4    ]) = fmul2(a[c][0], ss);
                    *reinterpret_cast<ull*>(&sm[OFF_TMP + (c4+c)*20 + rq*4 + 2]) = fmul2(a[c][1], ss);
                }
            }
        }
        __syncthreads();

        // ---- stage x_v (192 cols, transposed stride 20, STS.128) ----
        for (int u = t; u < 192*4; u += NTHR) {
            int c = u % 192, rq = u / 192;
            const float* xp = xg + (size_t)(r0 + rq*4)*480 + 128 + c;
            float4 v; v.x = xp[0]; v.y = xp[480]; v.z = xp[960]; v.w = xp[1440];
            *reinterpret_cast<float4*>(&sm[OFF_XS + c*20 + rq*4]) = v;
        }
        __syncthreads();

        // ---- op2: v_k -> vk_T; 2 cols x 2 rows per thread, i-split x2 ----
        {
            const int tl = t & 255;
            const int c2 = (tl & 31) * 2;        // 32 colpairs
            const int rg = tl >> 5;              // 8 rowgroups x 2 rows
            const int g  = t >> 8;               // i halves of 32
            ull a0[3] = {}, a1[3] = {};
            const float* W = W_l1 + k*64*64 + g*32*64;
            #pragma unroll 8
            for (int i = 0; i < 32; ++i) {
                const float2 w = *reinterpret_cast<const float2*>(&W[i*64 + c2]);
                ull w0 = pk2(w.x, w.x), w1 = pk2(w.y, w.y);
                #pragma unroll
                for (int m = 0; m < 3; ++m) {
                    ull xv = *reinterpret_cast<const ull*>(&sm[OFF_XS + ((g*32 + i)*3 + m)*20 + rg*2]);
                    a0[m] = ffma2(xv, w0, a0[m]);
                    a1[m] = ffma2(xv, w1, a1[m]);
                }
            }
            ull* sc2 = reinterpret_cast<ull*>(&sm[OFF_SCUR]);
            if (g == 1) {
                #pragma unroll
                for (int m = 0; m < 3; ++m) {
                    sc2[(m*2+0)*256 + tl] = a0[m];
                    sc2[(m*2+1)*256 + tl] = a1[m];
                }
            }
            __syncthreads();
            if (g == 0) {
                const ull ei = pk2(0.125f, 0.125f);
                #pragma unroll
                for (int m = 0; m < 3; ++m) {
                    a0[m] = fadd2(a0[m], sc2[(m*2+0)*256 + tl]);
                    a1[m] = fadd2(a1[m], sc2[(m*2+1)*256 + tl]);
                    *reinterpret_cast<ull*>(&vkbuf[((c2+0)*3 + m)*18 + rg*2]) = fmul2(a0[m], ei);
                    *reinterpret_cast<ull*>(&vkbuf[((c2+1)*3 + m)*18 + rg*2]) = fmul2(a1[m], ei);
                }
            }
        }
        __syncthreads();

        // ---- stage x_T split layout: [r][i][m0..3] + scalar plane [r][i] ----
        for (int u = t; u < ROWS*160; u += NTHR) {
            int r = u / 160, c = u - r*160;
            int i = c / 5, m = c - i*5;
            float v = xg[(size_t)(r0 + r)*480 + 320 + c];
            if (m < 4) sm[OFF_XS + r*128 + i*4 + m] = v;
            else       sm[OFF_XS + 2048 + r*32 + i] = v;
        }
        __syncthreads();

        // ---- op3 (all threads): n_k into TMP ----
        {
            int j = t & 31, r = t >> 5;
            float a[5] = {};
            const float* W = W_l2 + k*32*32;
            const float* xr4 = &sm[OFF_XS + r*128];
            const float* xr1 = &sm[OFF_XS + 2048 + r*32];
            #pragma unroll 8
            for (int i = 0; i < 32; ++i) {
                float w = __ldg(&W[i*32 + j]);
                const float4 xv = *reinterpret_cast<const float4*>(&xr4[i*4]);
                float xe = xr1[i];
                a[0] += xv.x*w; a[1] += xv.y*w; a[2] += xv.z*w; a[3] += xv.w*w; a[4] += xe*w;
            }
            float s2 = a[0]*a[0] + a[1]*a[1] + a[2]*a[2] + a[3]*a[3] + a[4]*a[4];
            sm[OFF_TMP + (128 + j)*20 + r] = sqrtf(s2)*0.17677669529663687f;
        }

        // ---- op4-GEMM: halves do u0 (W_tp0 -> VCUR) / u1 (W_tp1 -> SCUR); 2 cols x 2 rows ----
        if (k > 0) {
            const int half = t >> 8;
            const int tl = t & 255;
            const int c2 = (tl & 31) * 2;
            const int rg = tl >> 5;
            const float* Wtp = half ? W_tp1 : W_tp0;
            float* dst = half ? (sm + OFF_SCUR) : (sm + OFF_VCUR);
            ull u[2][3] = {};
            #pragma unroll 8
            for (int i = 0; i < 64; ++i) {
                const float2 w = *reinterpret_cast<const float2*>(&Wtp[i*64 + c2]);
                ull w0 = pk2(w.x, w.x), w1 = pk2(w.y, w.y);
                #pragma unroll
                for (int m = 0; m < 3; ++m) {
                    ull vp = *reinterpret_cast<const ull*>(&vkbuf[(i*3 + m)*18 + rg*2]);
                    u[0][m] = ffma2(vp, w0, u[0][m]);
                    u[1][m] = ffma2(vp, w1, u[1][m]);
                }
            }
            #pragma unroll
            for (int m = 0; m < 3; ++m) {
                *reinterpret_cast<ull*>(&dst[((c2+0)*3 + m)*18 + rg*2]) = u[0][m];
                *reinterpret_cast<ull*>(&dst[((c2+1)*3 + m)*18 + rg*2]) = u[1][m];
            }
        }
        __syncthreads();

        // ---- op4-reduce: p0/p1 per row (warps 0-7, 2 rows/warp) ----
        if (k > 0) {
            int w = t >> 5, lane = t & 31;
            if (w < 8) {
                int ra = 2*w, rb = 2*w + 1;
                float p0a=0,pxa=0,pya=0,pza=0, p0b=0,pxb=0,pyb=0,pzb=0;
                #pragma unroll
                for (int jj = 0; jj < 2; ++jj) {
                    int j = jj*32 + lane;
                    float u00 = sm[OFF_VCUR + (j*3+0)*18 + ra];
                    float u01 = sm[OFF_VCUR + (j*3+1)*18 + ra];
                    float u02 = sm[OFF_VCUR + (j*3+2)*18 + ra];
                    float u10 = sm[OFF_SCUR + (j*3+0)*18 + ra];
                    float u11 = sm[OFF_SCUR + (j*3+1)*18 + ra];
                    float u12 = sm[OFF_SCUR + (j*3+2)*18 + ra];
                    float vx = vpbuf[(j*3+0)*18 + ra];
                    float vy = vpbuf[(j*3+1)*18 + ra];
                    float vz = vpbuf[(j*3+2)*18 + ra];
                    p0a += u00*vx + u01*vy + u02*vz;
                    pxa += u11*vz - u12*vy;
                    pya += u12*vx - u10*vz;
                    pza += u10*vy - u11*vx;
                    u00 = sm[OFF_VCUR + (j*3+0)*18 + rb];
                    u01 = sm[OFF_VCUR + (j*3+1)*18 + rb];
                    u02 = sm[OFF_VCUR + (j*3+2)*18 + rb];
                    u10 = sm[OFF_SCUR + (j*3+0)*18 + rb];
                    u11 = sm[OFF_SCUR + (j*3+1)*18 + rb];
                    u12 = sm[OFF_SCUR + (j*3+2)*18 + rb];
                    vx = vpbuf[(j*3+0)*18 + rb];
                    vy = vpbuf[(j*3+1)*18 + rb];
                    vz = vpbuf[(j*3+2)*18 + rb];
                    p0b += u00*vx + u01*vy + u02*vz;
                    pxb += u11*vz - u12*vy;
                    pyb += u12*vx - u10*vz;
                    pzb += u10*vy - u11*vx;
                }
                #pragma unroll
                for (int off = 16; off > 0; off >>= 1) {
                    p0a += __shfl_down_sync(0xffffffffu, p0a, off);
                    pxa += __shfl_down_sync(0xffffffffu, pxa, off);
                    pya += __shfl_down_sync(0xffffffffu, pya, off);
                    pza += __shfl_down_sync(0xffffffffu, pza, off);
                    p0b += __shfl_down_sync(0xffffffffu, p0b, off);
                    pxb += __shfl_down_sync(0xffffffffu, pxb, off);
                    pyb += __shfl_down_sync(0xffffffffu, pyb, off);
                    pzb += __shfl_down_sync(0xffffffffu, pzb, off);
                }
                if (lane == 0) {
                    const float c0 = 0.009021097956087905f;
                    const float c1 = 0.011048543456039806f;
                    sm[OFF_TMP + 160*20 + ra] = p0a*c0;
                    sm[OFF_SP1 + ra*4 + 0] = pxa*c1;
                    sm[OFF_SP1 + ra*4 + 1] = pya*c1;
                    sm[OFF_SP1 + ra*4 + 2] = pza*c1;
                    sm[OFF_TMP + 160*20 + rb] = p0b*c0;
                    sm[OFF_SP1 + rb*4 + 0] = pxb*c1;
                    sm[OFF_SP1 + rb*4 + 1] = pyb*c1;
                    sm[OFF_SP1 + rb*4 + 2] = pzb*c1;
                }
            }
        } else {
            if (t < ROWS) {
                sm[OFF_TMP + 160*20 + t] = 0.f;
                sm[OFF_SP1 + t*4 + 0] = 0.f;
                sm[OFF_SP1 + t*4 + 1] = 0.f;
                sm[OFF_SP1 + t*4 + 2] = 0.f;
            }
        }
        __syncthreads();

        // ---- op5: s_tilde; 2 cols x 8 rows, i-split x2 (coalesced scratch); op6 on half 1 ----
        {
            const int tl = t & 255;
            const int c2 = (tl & 127) * 2;
            const int rh8 = (tl >> 7) * 8;
            const int g = t >> 8;
            const int ibeg = g ? 81 : 0;
            const int iend = g ? 161 : 81;
            ull aA[4] = {}, aB[4] = {};
            const float* W = Ws + k*161*256;
            #pragma unroll 8
            for (int i = ibeg; i < iend; ++i) {
                const float2 w = *reinterpret_cast<const float2*>(&W[i*256 + c2]);
                ull wx = pk2(w.x, w.x), wy = pk2(w.y, w.y);
                const ulonglong2 xa = *reinterpret_cast<const ulonglong2*>(&sm[OFF_TMP + i*20 + rh8]);
                const ulonglong2 xb = *reinterpret_cast<const ulonglong2*>(&sm[OFF_TMP + i*20 + rh8 + 4]);
                aA[0] = ffma2(xa.x, wx, aA[0]);
                aA[1] = ffma2(xa.y, wx, aA[1]);
                aA[2] = ffma2(xb.x, wx, aA[2]);
                aA[3] = ffma2(xb.y, wx, aA[3]);
                aB[0] = ffma2(xa.x, wy, aB[0]);
                aB[1] = ffma2(xa.y, wy, aB[1]);
                aB[2] = ffma2(xb.x, wy, aB[2]);
                aB[3] = ffma2(xb.y, wy, aB[3]);
            }
            // coalesced partial scratch: chunk q = [256 threads x 4 floats]
            if (g == 1) {
                ulonglong2 s;
                s.x = aA[0]; s.y = aA[1];
                *reinterpret_cast<ulonglong2*>(&vpbuf[0*1024 + tl*4]) = s;
                s.x = aA[2]; s.y = aA[3];
                *reinterpret_cast<ulonglong2*>(&vpbuf[1*1024 + tl*4]) = s;
                s.x = aB[0]; s.y = aB[1];
                *reinterpret_cast<ulonglong2*>(&vpbuf[2*1024 + tl*4]) = s;
                s.x = aB[2]; s.y = aB[3];
                *reinterpret_cast<ulonglong2*>(&sm[OFF_MBUF + tl*4]) = s;
            }
            __syncthreads();
            if (g == 0) {
                ulonglong2 s;
                s = *reinterpret_cast<const ulonglong2*>(&vpbuf[0*1024 + tl*4]);
                aA[0] = fadd2(aA[0], s.x); aA[1] = fadd2(aA[1], s.y);
                s = *reinterpret_cast<const ulonglong2*>(&vpbuf[1*1024 + tl*4]);
                aA[2] = fadd2(aA[2], s.x); aA[3] = fadd2(aA[3], s.y);
                s = *reinterpret_cast<const ulonglong2*>(&vpbuf[2*1024 + tl*4]);
                aB[0] = fadd2(aB[0], s.x); aB[1] = fadd2(aB[1], s.y);
                s = *reinterpret_cast<const ulonglong2*>(&sm[OFF_MBUF + tl*4]);
                aB[2] = fadd2(aB[2], s.x); aB[3] = fadd2(aB[3], s.y);
                const float2 bb = *reinterpret_cast<const float2*>(&bs[k*256 + c2]);
                #pragma unroll
                for (int q = 0; q < 4; ++q) {
                    float alo, ahi, blo, bhi;
                    upk2(alo, ahi, aA[q]); upk2(blo, bhi, aB[q]);
                    float2 o;
                    o.x = alo + bb.x; o.y = blo + bb.y;
                    *reinterpret_cast<float2*>(&sm[OFF_SCUR + (rh8 + q*2    )*256 + c2]) = o;
                    o.x = ahi + bb.x; o.y = bhi + bb.y;
                    *reinterpret_cast<float2*>(&sm[OFF_SCUR + (rh8 + q*2 + 1)*256 + c2]) = o;
                }
            } else {
                // ---- op6 on threads 256-511: 2 cols x 2 rows per thread ----
                const int c6 = (tl & 31) * 2;
                const int rg = tl >> 5;              // 8 rowgroups x 2 rows
                ull a0[3] = {}, a1[3] = {};
                const float* W6 = Wv1o + k*64*64;
                #pragma unroll 8
                for (int i = 0; i < 64; ++i) {
                    const float2 w = *reinterpret_cast<const float2*>(&W6[i*64 + c6]);
                    ull w0 = pk2(w.x, w.x), w1 = pk2(w.y, w.y);
                    #pragma unroll
                    for (int m = 0; m < 3; ++m) {
                        ull vp = *reinterpret_cast<const ull*>(&vkbuf[(i*3 + m)*18 + rg*2]);
                        a0[m] = ffma2(vp, w0, a0[m]);
                        a1[m] = ffma2(vp, w1, a1[m]);
                    }
                }
                const float2 we = *reinterpret_cast<const float2*>(&Wv1e[k*64 + c6]);
                int ra = rg*2, rb = rg*2 + 1;
                #pragma unroll
                for (int m = 0; m < 3; ++m) {
                    float va, vb;
                    upk2(va, vb, a0[m]);
                    sm[OFF_VCUR + ra*384 + (c6+0)*3 + m] = va*0.125f;
                    sm[OFF_VCUR + rb*384 + (c6+0)*3 + m] = vb*0.125f;
                    upk2(va, vb, a1[m]);
                    sm[OFF_VCUR + ra*384 + (c6+1)*3 + m] = va*0.125f;
                    sm[OFF_VCUR + rb*384 + (c6+1)*3 + m] = vb*0.125f;
                    sm[OFF_VCUR + ra*384 + 192 + (c6+0)*3 + m] = sm[OFF_SP1 + ra*4 + m]*we.x;
                    sm[OFF_VCUR + rb*384 + 192 + (c6+0)*3 + m] = sm[OFF_SP1 + rb*4 + m]*we.x;
                    sm[OFF_VCUR + ra*384 + 192 + (c6+1)*3 + m] = sm[OFF_SP1 + ra*4 + m]*we.y;
                    sm[OFF_VCUR + rb*384 + 192 + (c6+1)*3 + m] = sm[OFF_SP1 + rb*4 + m]*we.y;
                }
            }
        }
        __syncthreads();

        // ---- layernorm (warp per row) w/ fused m-norms; writes h TRANSPOSED (stride 18) ----
        {
            int r = t >> 5, lane = t & 31;
            float s = 0.f, s2 = 0.f;
            #pragma unroll
            for (int c = lane; c < 384; c += 32) {
                float v;
                if (c < 256) v = sm[OFF_SCUR + r*256 + c];
                else {
                    int idx = c - 256;
                    float a = sm[OFF_VCUR + r*384 + idx*3];
                    float b = sm[OFF_VCUR + r*384 + idx*3 + 1];
                    float d = sm[OFF_VCUR + r*384 + idx*3 + 2];
                    v = sqrtf(a*a + b*b + d*d);
                    sm[OFF_MBUF + r*128 + idx] = v;
                }
                s += v; s2 += v*v;
            }
            #pragma unroll
            for (int off = 16; off > 0; off >>= 1) {
                s  += __shfl_xor_sync(0xffffffffu, s,  off);
                s2 += __shfl_xor_sync(0xffffffffu, s2, off);
            }
            float mu   = s  * (1.f/384.f);
            float var  = s2 * (1.f/384.f) - mu*mu;
            float rstd = rsqrtf(var + 1e-5f);
            #pragma unroll
            for (int c = lane; c < 384; c += 32) {
                float v = (c < 256) ? sm[OFF_SCUR + r*256 + c] : sm[OFF_MBUF + r*128 + c - 256];
                sm[OFF_HBUF + c*18 + r] = (v - mu)*rstd*sm[OFF_GB + c] + sm[OFF_GB + 384 + c];
            }
        }
        // spill S,V (float4, all threads)
        for (int idx = t; idx < ROWS*160; idx += NTHR) {
            int r = idx / 160, q = idx - r*160;
            float4 v;
            if (q < 64) v = *reinterpret_cast<const float4*>(&sm[OFF_SCUR + r*256 + q*4]);
            else        v = *reinterpret_cast<const float4*>(&sm[OFF_VCUR + r*384 + (q - 64)*4]);
            *reinterpret_cast<float4*>(&g_SV[(size_t)(r0 + r)*2560 + (size_t)k*640 + q*4]) = v;
        }
        __syncthreads();

        // ---- MLP: 4 cols x 4 rows, i-split x8, coalesced combine, butterfly finish ----
        {
            const int tl = t & 63;
            const int c4 = (tl & 15) * 4;
            const int rg = tl >> 4;
            const int g  = t >> 6;
            ull a[4][2] = {};
            const float* Wp = Wm1 + g*48*64;
            #pragma unroll 6
            for (int i = 0; i < 48; ++i) {
                const float4 w4 = *reinterpret_cast<const float4*>(&Wp[i*64 + c4]);
                const ull h0 = *reinterpret_cast<const ull*>(&sm[OFF_HBUF + (g*48 + i)*18 + rg*4]);
                const ull h1 = *reinterpret_cast<const ull*>(&sm[OFF_HBUF + (g*48 + i)*18 + rg*4 + 2]);
                ull ww;
                ww = pk2(w4.x, w4.x); a[0][0]=ffma2(h0,ww,a[0][0]); a[0][1]=ffma2(h1,ww,a[0][1]);
                ww = pk2(w4.y, w4.y); a[1][0]=ffma2(h0,ww,a[1][0]); a[1][1]=ffma2(h1,ww,a[1][1]);
                ww = pk2(w4.z, w4.z); a[2][0]=ffma2(h0,ww,a[2][0]); a[2][1]=ffma2(h1,ww,a[2][1]);
                ww = pk2(w4.w, w4.w); a[3][0]=ffma2(h0,ww,a[3][0]); a[3][1]=ffma2(h1,ww,a[3][1]);
            }
            ull* sc = reinterpret_cast<ull*>(&sm[OFF_SCUR]);
            if (g > 0) {
                #pragma unroll
                for (int c = 0; c < 4; ++c) {
                    ulonglong2 s; s.x = a[c][0]; s.y = a[c][1];
                    *reinterpret_cast<ulonglong2*>(&sc[(c*448 + (g-1)*64 + tl)*2]) = s;
                }
            }
            __syncthreads();
            if (g == 0) {
                #pragma unroll
                for (int gg = 0; gg < 7; ++gg)
                    #pragma unroll
                    for (int c = 0; c < 4; ++c) {
                        const ulonglong2 s = *reinterpret_cast<const ulonglong2*>(&sc[(c*448 + gg*64 + tl)*2]);
                        a[c][0] = fadd2(a[c][0], s.x);
                        a[c][1] = fadd2(a[c][1], s.y);
                    }
                float er[4] = {0.f, 0.f, 0.f, 0.f};
                #pragma unroll
                for (int c = 0; c < 4; ++c) {
                    float b1c  = sm[OFF_BM1 + c4 + c];
                    float wm2c = sm[OFF_WM2 + c4 + c];
                    float v0,v1,v2,v3;
                    upk2(v0, v1, a[c][0]); upk2(v2, v3, a[c][1]);
                    float z;
                    z = v0 + b1c; er[0] += z/(1.f + expf(-z))*wm2c;
                    z = v1 + b1c; er[1] += z/(1.f + expf(-z))*wm2c;
                    z = v2 + b1c; er[2] += z/(1.f + expf(-z))*wm2c;
                    z = v3 + b1c; er[3] += z/(1.f + expf(-z))*wm2c;
                }
                #pragma unroll
                for (int m = 8; m >= 1; m >>= 1)
                    #pragma unroll
                    for (int r = 0; r < 4; ++r)
                        er[r] += __shfl_xor_sync(0xffffffffu, er[r], m);
                if ((tl & 15) == 0) {
                    #pragma unroll
                    for (int r = 0; r < 4; ++r)
                        sm[OFF_EV + (rg*4 + r)*4 + k] = er[r];
                }
            }
        }

        { float* tp = vkbuf; vkbuf = vpbuf; vpbuf = tp; }
        __syncthreads();
    }

    // ---- softmax over K (bm2 cancels); alpha in place ----
    if (t < ROWS) {
        float e0 = sm[OFF_EV + t*4 + 0], e1 = sm[OFF_EV + t*4 + 1];
        float e2 = sm[OFF_EV + t*4 + 2], e3 = sm[OFF_EV + t*4 + 3];
        float mx = fmaxf(fmaxf(e0, e1), fmaxf(e2, e3));
        float z0 = expf(e0 - mx), z1 = expf(e1 - mx), z2 = expf(e2 - mx), z3 = expf(e3 - mx);
        float inv = 1.f/(z0 + z1 + z2 + z3);
        sm[OFF_EV + t*4 + 0] = z0*inv;
        sm[OFF_EV + t*4 + 1] = z1*inv;
        sm[OFF_EV + t*4 + 2] = z2*inv;
        sm[OFF_EV + t*4 + 3] = z3*inv;
    }
    __syncthreads();

    // ---- fused epilogue: out = sum_k alpha_k * SV_k (L2-hot) ----
    for (int idx = t; idx < ROWS*160; idx += NTHR) {
        int r = idx / 160, q = idx - r*160;
        const float* sv = g_SV + (size_t)(r0 + r)*2560 + q*4;
        const float a0 = sm[OFF_EV + r*4 + 0], a1 = sm[OFF_EV + r*4 + 1];
        const float a2 = sm[OFF_EV + r*4 + 2], a3 = sm[OFF_EV + r*4 + 3];
        const float4 v0 = *reinterpret_cast<const float4*>(sv);
        const float4 v1 = *reinterpret_cast<const float4*>(sv + 640);
        const float4 v2 = *reinterpret_cast<const float4*>(sv + 1280);
        const float4 v3 = *reinterpret_cast<const float4*>(sv + 1920);
        float4 o;
        o.x = a0*v0.x + a1*v1.x + a2*v2.x + a3*v3.x;
        o.y = a0*v0.y + a1*v1.y + a2*v2.y + a3*v3.y;
        o.z = a0*v0.z + a1*v1.z + a2*v2.z + a3*v3.z;
        o.w = a0*v0.w + a1*v1.w + a2*v2.w + a3*v3.w;
        if (q < 64) *reinterpret_cast<float4*>(&out[(size_t)(r0 + r)*256 + q*4]) = o;
        else        *reinterpret_cast<float4*>(&out[(size_t)NTOK*256 + (size_t)(r0 + r)*384 + (q - 64)*4]) = o;
    }
}

extern "C" void kernel_launch(void* const* d_in, const int* in_sizes, int n_in,
                              void* d_out, int out_size)
{
    (void)in_sizes; (void)n_in; (void)out_size;
    cudaFuncSetAttribute(fuse_k1, cudaFuncAttributeMaxDynamicSharedMemorySize, SMEM_BYTES);

    fuse_k1<<<NTOK/ROWS, NTHR, SMEM_BYTES>>>(
        (const float*)d_in[0],  (const float*)d_in[1],  (const float*)d_in[2],
        (const float*)d_in[3],  (const float*)d_in[4],  (const float*)d_in[5],
        (const float*)d_in[6],  (const float*)d_in[7],  (const float*)d_in[8],
        (const float*)d_in[9],  (const float*)d_in[10], (const float*)d_in[11],
        (const float*)d_in[12], (const float*)d_in[13], (const float*)d_in[14],
        (const float*)d_in[15], (const float*)d_in[16], (const float*)d_in[17],
        (const float*)d_in[18], (float*)d_out);
}